// round 7
// baseline (speedup 1.0000x reference)
#include <cuda_runtime.h>
#include <cstdint>

// Problem constants
#define T_SEQ 2048
#define EMB   2048
#define NH    32
#define HD    64

// -------- scratch (device globals; no allocation allowed) --------
__device__ float g_Q[T_SEQ * EMB];   // q projection (pre-rounded, scaled by 0.125*log2e)
__device__ float g_K[T_SEQ * HD];    // k projection (pre-rounded)
__device__ float g_V[T_SEQ * HD];    // v projection (pre-rounded)
__device__ float g_A[T_SEQ * EMB];   // attention output (pre-rounded)
__device__ float g_x [T_SEQ * EMB];  // tf32-rounded x
__device__ float g_wq[EMB * EMB];    // tf32-rounded Wq
__device__ float g_wo[EMB * EMB];    // tf32-rounded Wo
__device__ float g_wk[HD * EMB];     // tf32-rounded Wk
__device__ float g_wv[HD * EMB];     // tf32-rounded Wv

#define LOG2E 1.4426950408889634f

// ============================================================
// helpers
// ============================================================
__device__ __forceinline__ uint32_t smem_u32(const void* p) {
    uint32_t a;
    asm("{ .reg .u64 t; cvta.to.shared.u64 t, %1; cvt.u32.u64 %0, t; }" : "=r"(a) : "l"(p));
    return a;
}
__device__ __forceinline__ uint32_t f2tf32(float x) {
    uint32_t r;
    asm("cvt.rna.tf32.f32 %0, %1;" : "=r"(r) : "f"(x));
    return r;
}
__device__ __forceinline__ float rnd(float x) { return __uint_as_float(f2tf32(x)); }
__device__ __forceinline__ float fex2(float x) {
    float r;
    asm("ex2.approx.f32 %0, %1;" : "=f"(r) : "f"(x));
    return r;
}
__device__ __forceinline__ void cp16(uint32_t dst, const void* src) {
    asm volatile("cp.async.cg.shared.global [%0], [%1], 16;" :: "r"(dst), "l"(src) : "memory");
}
__device__ __forceinline__ void mma_tf32(float& d0, float& d1, float& d2, float& d3,
                                         uint32_t a0, uint32_t a1, uint32_t a2, uint32_t a3,
                                         uint32_t b0, uint32_t b1) {
    asm volatile("mma.sync.aligned.m16n8k8.row.col.f32.tf32.tf32.f32 "
                 "{%0,%1,%2,%3}, {%4,%5,%6,%7}, {%8,%9}, {%0,%1,%2,%3};"
                 : "+f"(d0), "+f"(d1), "+f"(d2), "+f"(d3)
                 : "r"(a0), "r"(a1), "r"(a2), "r"(a3), "r"(b0), "r"(b1));
}

// ============================================================
// tf32 rounding pre-pass
// ============================================================
__global__ void round_pass(const float4* __restrict__ src, float4* __restrict__ dst, int n4) {
    for (int i = blockIdx.x * blockDim.x + threadIdx.x; i < n4; i += gridDim.x * blockDim.x) {
        float4 v = src[i];
        v.x = rnd(v.x); v.y = rnd(v.y); v.z = rnd(v.z); v.w = rnd(v.w);
        dst[i] = v;
    }
}

// ============================================================
// tf32 mma.sync GEMM:  C[M,N] = A[M,K] @ B[N,K]^T
// 3-stage cp.async pipeline, ONE __syncthreads per k-chunk.
// Inputs pre-rounded to tf32.
// ============================================================
#define BKF 32
#define LDA 36
#define OPER_F (128 * LDA)                    // floats per operand tile (4608)
#define STAGE_F (2 * OPER_F)                  // A+B per stage
#define GEMM_SMEM (3 * STAGE_F * 4)           // 110592 bytes

__global__ __launch_bounds__(256, 2) void gemm_tf32mma(
    const float* __restrict__ A, const float* __restrict__ B0,
    const float* __restrict__ B1, float* __restrict__ C0,
    float* __restrict__ C1, int K, int N, int dual,
    int do_round, float oscale) {
    extern __shared__ float sm[];
    const int tid  = threadIdx.x;
    const int wid  = tid >> 5;
    const int lane = tid & 31;
    const int wm   = wid & 1;
    const int wn   = wid >> 1;
    const int m0   = blockIdx.y * 128;
    const int n0   = blockIdx.x * 128;
    const int g    = lane >> 2;
    const int tig  = lane & 3;

    float acc[4][4][4];
#pragma unroll
    for (int i = 0; i < 4; i++)
#pragma unroll
        for (int j = 0; j < 4; j++)
#pragma unroll
            for (int r = 0; r < 4; r++) acc[i][j][r] = 0.f;

    const int NT = K / BKF;

    auto stage = [&](int t) {
        const int b = t % 3;
        float* dstA = sm + b * STAGE_F;
        float* dstB = dstA + OPER_F;
#pragma unroll
        for (int u = 0; u < 4; u++) {
            int idx = u * 256 + tid;
            int r = idx >> 3, c4 = idx & 7;
            cp16(smem_u32(dstA + r * LDA + c4 * 4),
                 A + (size_t)(m0 + r) * K + t * BKF + c4 * 4);
            const float* gb;
            if (dual) gb = (r < 64 ? B0 + (size_t)r * K : B1 + (size_t)(r - 64) * K)
                           + t * BKF + c4 * 4;
            else      gb = B0 + (size_t)(n0 + r) * K + t * BKF + c4 * 4;
            cp16(smem_u32(dstB + r * LDA + c4 * 4), gb);
        }
        asm volatile("cp.async.commit_group;" ::: "memory");
    };

    stage(0);
    if (NT > 1) stage(1);

    for (int t = 0; t < NT; t++) {
        if (t < NT - 1) asm volatile("cp.async.wait_group 1;" ::: "memory");
        else            asm volatile("cp.async.wait_group 0;" ::: "memory");
        __syncthreads();                       // stage(t) visible; compute(t-1) closed
        if (t + 2 < NT) stage(t + 2);          // overwrites buf (t-1)%3 — safe

        const float* sA = sm + (t % 3) * STAGE_F + (wm * 64) * LDA;
        const float* sB = sm + (t % 3) * STAGE_F + OPER_F + (wn * 32) * LDA;

#pragma unroll
        for (int ks = 0; ks < 4; ks++) {
            uint32_t bf[4][2];
#pragma unroll
            for (int nt = 0; nt < 4; nt++) {
                const float* bp = sB + (nt * 8 + g) * LDA + ks * 8 + tig;
                bf[nt][0] = __float_as_uint(bp[0]);
                bf[nt][1] = __float_as_uint(bp[4]);
            }
            uint32_t af[4][4];
#pragma unroll
            for (int mt = 0; mt < 4; mt++) {
                const float* ap = sA + (mt * 16 + g) * LDA + ks * 8 + tig;
                af[mt][0] = __float_as_uint(ap[0]);
                af[mt][1] = __float_as_uint(ap[8 * LDA]);
                af[mt][2] = __float_as_uint(ap[4]);
                af[mt][3] = __float_as_uint(ap[8 * LDA + 4]);
            }
#pragma unroll
            for (int mt = 0; mt < 4; mt++)
#pragma unroll
                for (int nt = 0; nt < 4; nt++)
                    mma_tf32(acc[mt][nt][0], acc[mt][nt][1], acc[mt][nt][2], acc[mt][nt][3],
                             af[mt][0], af[mt][1], af[mt][2], af[mt][3],
                             bf[nt][0], bf[nt][1]);
        }
    }

#pragma unroll
    for (int mt = 0; mt < 4; mt++) {
        const int row0 = m0 + wm * 64 + mt * 16 + g;
#pragma unroll
        for (int nt = 0; nt < 4; nt++) {
            float v0 = acc[mt][nt][0] * oscale, v1 = acc[mt][nt][1] * oscale;
            float v2 = acc[mt][nt][2] * oscale, v3 = acc[mt][nt][3] * oscale;
            if (do_round) { v0 = rnd(v0); v1 = rnd(v1); v2 = rnd(v2); v3 = rnd(v3); }
            const int colL = wn * 32 + nt * 8 + 2 * tig;
            if (dual) {
                float* dst = (colL < 64) ? C0 : C1;
                const int c = (colL < 64) ? colL : colL - 64;
                *(float2*)(dst + (size_t)row0 * 64 + c)       = make_float2(v0, v1);
                *(float2*)(dst + (size_t)(row0 + 8) * 64 + c) = make_float2(v2, v3);
            } else {
                const int col = n0 + colL;
                *(float2*)(C0 + (size_t)row0 * N + col)       = make_float2(v0, v1);
                *(float2*)(C0 + (size_t)(row0 + 8) * N + col) = make_float2(v2, v3);
            }
        }
    }
}

// ============================================================
// Flash attention, mma.sync tf32, log2-domain softmax,
// double-buffered K/V with ONE __syncthreads per tile.
// Q pre-scaled by 0.125*log2e; slope' = slope*log2e.
// ============================================================
#define SPK 68
#define SPV 72
#define SPP 68
#define KBUF_F (64 * SPK)
#define VBUF_F (64 * SPV)
#define ATT_SMEM ((2 * KBUF_F + 2 * VBUF_F + 128 * SPP) * 4)   // 106496 B

__global__ __launch_bounds__(256) void attn_mma(const float* __restrict__ Q,
                                                const float* __restrict__ Kg,
                                                const float* __restrict__ Vg,
                                                float* __restrict__ O) {
    extern __shared__ float sm[];
    float* Kb[2] = { sm, sm + KBUF_F };
    float* Vb[2] = { sm + 2 * KBUF_F, sm + 2 * KBUF_F + VBUF_F };
    float* P = sm + 2 * KBUF_F + 2 * VBUF_F;   // [128][SPP]

    const int h   = blockIdx.y;
    const int q0  = blockIdx.x * 128;
    const int tid = threadIdx.x;
    const int wid = tid >> 5;
    const int lane = tid & 31;
    const int g   = lane >> 2;
    const int tig = lane & 3;
    const float slope2 = exp2f(-0.25f * (float)(h + 1)) * LOG2E;

    auto prefetch = [&](int t) {
        const int b = t & 1;
        const int j0 = t * 64;
#pragma unroll
        for (int u = 0; u < 4; u++) {
            int idx = u * 256 + tid;
            int r = idx >> 4, c4 = idx & 15;
            cp16(smem_u32(Kb[b] + r * SPK + c4 * 4), Kg + (size_t)(j0 + r) * HD + c4 * 4);
            cp16(smem_u32(Vb[b] + r * SPV + c4 * 4), Vg + (size_t)(j0 + r) * HD + c4 * 4);
        }
        asm volatile("cp.async.commit_group;" ::: "memory");
    };

    prefetch(0);

    // ---- stage Q tile into P region, then load A-fragments ----
#pragma unroll
    for (int u = 0; u < 8; u++) {
        int idx = u * 256 + tid;
        int r = idx >> 4, c4 = idx & 15;
        *(float4*)(P + r * SPP + c4 * 4) =
            *(const float4*)(Q + (size_t)(q0 + r) * EMB + h * HD + c4 * 4);
    }
    __syncthreads();

    uint32_t qf[8][4];
    {
        const float* PW = P + wid * 16 * SPP;
#pragma unroll
        for (int ks = 0; ks < 8; ks++) {
            const int k = ks * 8 + tig;
            qf[ks][0] = __float_as_uint(PW[g * SPP + k]);
            qf[ks][1] = __float_as_uint(PW[(g + 8) * SPP + k]);
            qf[ks][2] = __float_as_uint(PW[g * SPP + k + 4]);
            qf[ks][3] = __float_as_uint(PW[(g + 8) * SPP + k + 4]);
        }
    }

    float oacc[8][4];
#pragma unroll
    for (int nt = 0; nt < 8; nt++)
#pragma unroll
        for (int r = 0; r < 4; r++) oacc[nt][r] = 0.f;

    float m0r = -1e30f, m1r = -1e30f;
    float l0 = 0.f, l1 = 0.f;
    const int i0 = q0 + wid * 16 + g;
    const int i1 = i0 + 8;
    float* PWm  = P + (wid * 16 + g) * SPP;
    float* PWm8 = PWm + 8 * SPP;

    const int NTILE = (q0 + 128) / 64;

    for (int t = 0; t < NTILE; t++) {
        const int j0 = t * 64;
        const float* Ksh = Kb[t & 1];
        const float* Vsh = Vb[t & 1];

        asm volatile("cp.async.wait_group 0;" ::: "memory");
        __syncthreads();                 // tile t visible; compute(t-1) closed
        if (t + 1 < NTILE) prefetch(t + 1);   // in flight during compute(t)

        // ---- S = Q @ K^T (log2 domain) ----
        float sacc[8][4];
#pragma unroll
        for (int nt = 0; nt < 8; nt++)
#pragma unroll
            for (int r = 0; r < 4; r++) sacc[nt][r] = 0.f;

#pragma unroll
        for (int ks = 0; ks < 8; ks++) {
#pragma unroll
            for (int nt = 0; nt < 8; nt++) {
                const float* kp = Ksh + (nt * 8 + g) * SPK + ks * 8 + tig;
                uint32_t b0 = __float_as_uint(kp[0]);
                uint32_t b1 = __float_as_uint(kp[4]);
                mma_tf32(sacc[nt][0], sacc[nt][1], sacc[nt][2], sacc[nt][3],
                         qf[ks][0], qf[ks][1], qf[ks][2], qf[ks][3], b0, b1);
            }
        }

        // ---- ALiBi + causal mask, tile max ----
        float mx0 = -1e30f, mx1 = -1e30f;
#pragma unroll
        for (int nt = 0; nt < 8; nt++) {
            const int jb = j0 + nt * 8 + 2 * tig;
            float v0 = (jb     <= i0) ? fmaf(slope2, (float)(jb     - i0), sacc[nt][0]) : -1e30f;
            float v1 = (jb + 1 <= i0) ? fmaf(slope2, (float)(jb + 1 - i0), sacc[nt][1]) : -1e30f;
            float v2 = (jb     <= i1) ? fmaf(slope2, (float)(jb     - i1), sacc[nt][2]) : -1e30f;
            float v3 = (jb + 1 <= i1) ? fmaf(slope2, (float)(jb + 1 - i1), sacc[nt][3]) : -1e30f;
            sacc[nt][0] = v0; sacc[nt][1] = v1; sacc[nt][2] = v2; sacc[nt][3] = v3;
            mx0 = fmaxf(mx0, fmaxf(v0, v1));
            mx1 = fmaxf(mx1, fmaxf(v2, v3));
        }
        mx0 = fmaxf(mx0, __shfl_xor_sync(0xffffffffu, mx0, 1));
        mx0 = fmaxf(mx0, __shfl_xor_sync(0xffffffffu, mx0, 2));
        mx1 = fmaxf(mx1, __shfl_xor_sync(0xffffffffu, mx1, 1));
        mx1 = fmaxf(mx1, __shfl_xor_sync(0xffffffffu, mx1, 2));

        const float mn0 = fmaxf(m0r, mx0);
        const float mn1 = fmaxf(m1r, mx1);
        const float a0 = fex2(m0r - mn0);
        const float a1 = fex2(m1r - mn1);

        float ps0 = 0.f, ps1 = 0.f;
#pragma unroll
        for (int nt = 0; nt < 8; nt++) {
            float e0 = fex2(sacc[nt][0] - mn0);
            float e1 = fex2(sacc[nt][1] - mn0);
            float e2 = fex2(sacc[nt][2] - mn1);
            float e3 = fex2(sacc[nt][3] - mn1);
            ps0 += e0 + e1;
            ps1 += e2 + e3;
            const int col = nt * 8 + 2 * tig;
            *(float2*)(PWm  + col) = make_float2(rnd(e0), rnd(e1));
            *(float2*)(PWm8 + col) = make_float2(rnd(e2), rnd(e3));
        }
        ps0 += __shfl_xor_sync(0xffffffffu, ps0, 1);
        ps0 += __shfl_xor_sync(0xffffffffu, ps0, 2);
        ps1 += __shfl_xor_sync(0xffffffffu, ps1, 1);
        ps1 += __shfl_xor_sync(0xffffffffu, ps1, 2);
        l0 = l0 * a0 + ps0;
        l1 = l1 * a1 + ps1;
#pragma unroll
        for (int nt = 0; nt < 8; nt++) {
            oacc[nt][0] *= a0; oacc[nt][1] *= a0;
            oacc[nt][2] *= a1; oacc[nt][3] *= a1;
        }
        m0r = mn0; m1r = mn1;
        __syncwarp();

        // ---- O += P @ V ----
        const float* PW = P + wid * 16 * SPP;
#pragma unroll
        for (int ks = 0; ks < 8; ks++) {
            const int k = ks * 8 + tig;
            uint32_t pa0 = __float_as_uint(PW[g * SPP + k]);
            uint32_t pa1 = __float_as_uint(PW[(g + 8) * SPP + k]);
            uint32_t pa2 = __float_as_uint(PW[g * SPP + k + 4]);
            uint32_t pa3 = __float_as_uint(PW[(g + 8) * SPP + k + 4]);
#pragma unroll
            for (int nt = 0; nt < 8; nt++) {
                const float* vp = Vsh + (ks * 8 + tig) * SPV + nt * 8 + g;
                uint32_t b0 = __float_as_uint(vp[0]);
                uint32_t b1 = __float_as_uint(vp[4 * SPV]);
                mma_tf32(oacc[nt][0], oacc[nt][1], oacc[nt][2], oacc[nt][3],
                         pa0, pa1, pa2, pa3, b0, b1);
            }
        }
    }

    // ---- normalize + store (rounded for the final GEMM) ----
    const float inv0 = 1.0f / l0;
    const float inv1 = 1.0f / l1;
    const int row0 = q0 + wid * 16 + g;
#pragma unroll
    for (int nt = 0; nt < 8; nt++) {
        const int col = h * HD + nt * 8 + 2 * tig;
        *(float2*)(O + (size_t)row0 * EMB + col) =
            make_float2(rnd(oacc[nt][0] * inv0), rnd(oacc[nt][1] * inv0));
        *(float2*)(O + (size_t)(row0 + 8) * EMB + col) =
            make_float2(rnd(oacc[nt][2] * inv1), rnd(oacc[nt][3] * inv1));
    }
}

// ============================================================
// launch
// ============================================================
extern "C" void kernel_launch(void* const* d_in, const int* in_sizes, int n_in,
                              void* d_out, int out_size) {
    (void)in_sizes; (void)n_in; (void)out_size;
    const float* x  = (const float*)d_in[0];
    const float* Wq = (const float*)d_in[1];
    const float* Wk = (const float*)d_in[2];
    const float* Wv = (const float*)d_in[3];
    const float* Wo = (const float*)d_in[4];
    float* out = (float*)d_out;

    void *pQ, *pK, *pV, *pA, *px, *pwq, *pwo, *pwk, *pwv;
    cudaGetSymbolAddress(&pQ, g_Q);
    cudaGetSymbolAddress(&pK, g_K);
    cudaGetSymbolAddress(&pV, g_V);
    cudaGetSymbolAddress(&pA, g_A);
    cudaGetSymbolAddress(&px, g_x);
    cudaGetSymbolAddress(&pwq, g_wq);
    cudaGetSymbolAddress(&pwo, g_wo);
    cudaGetSymbolAddress(&pwk, g_wk);
    cudaGetSymbolAddress(&pwv, g_wv);
    float* Qd = (float*)pQ;  float* Kd = (float*)pK;
    float* Vd = (float*)pV;  float* Ad = (float*)pA;
    float* xr = (float*)px;  float* wqr = (float*)pwq;
    float* wor = (float*)pwo; float* wkr = (float*)pwk; float* wvr = (float*)pwv;

    cudaFuncSetAttribute(gemm_tf32mma, cudaFuncAttributeMaxDynamicSharedMemorySize, GEMM_SMEM);
    cudaFuncSetAttribute(attn_mma, cudaFuncAttributeMaxDynamicSharedMemorySize, ATT_SMEM);

    // tf32 rounding pre-pass
    round_pass<<<1184, 256>>>((const float4*)x,  (float4*)xr,  T_SEQ * EMB / 4);
    round_pass<<<1184, 256>>>((const float4*)Wq, (float4*)wqr, EMB * EMB / 4);
    round_pass<<<1184, 256>>>((const float4*)Wo, (float4*)wor, EMB * EMB / 4);
    round_pass<<<128,  256>>>((const float4*)Wk, (float4*)wkr, HD * EMB / 4);
    round_pass<<<128,  256>>>((const float4*)Wv, (float4*)wvr, HD * EMB / 4);

    // Q projection (epilogue: round + scale by D^-1/2 * log2e)
    gemm_tf32mma<<<dim3(EMB / 128, T_SEQ / 128), 256, GEMM_SMEM>>>(
        xr, wqr, nullptr, Qd, nullptr, EMB, EMB, 0, 1, 0.125f * LOG2E);
    // K/V projections fused (epilogue: round)
    gemm_tf32mma<<<dim3(1, T_SEQ / 128), 256, GEMM_SMEM>>>(
        xr, wkr, wvr, Kd, Vd, EMB, 128, 1, 1, 1.0f);
    // attention
    attn_mma<<<dim3(T_SEQ / 128, NH), 256, ATT_SMEM>>>(Qd, Kd, Vd, Ad);
    // output projection (plain fp32 epilogue)
    gemm_tf32mma<<<dim3(EMB / 128, T_SEQ / 128), 256, GEMM_SMEM>>>(
        Ad, wor, nullptr, out, nullptr, EMB, EMB, 0, 0, 1.0f);
}

// round 8
// speedup vs baseline: 1.3172x; 1.3172x over previous
#include <cuda_runtime.h>
#include <cstdint>

#define T_SEQ 2048
#define EMB   2048
#define NH    32
#define HD    64
#define LOG2E 1.4426950408889634f

// -------- scratch (device globals) --------
__device__ float g_Q[T_SEQ * EMB];      // q proj (scaled by 0.125*log2e, rounded)
__device__ float g_K[T_SEQ * HD];       // k proj (rounded)
__device__ float g_V[T_SEQ * HD];       // v proj (rounded)
__device__ float g_A[T_SEQ * EMB];      // attention out (rounded, K-permuted cols)
__device__ float g_x [T_SEQ * EMB];     // x  rounded+permuted
__device__ float g_wq[EMB * EMB];       // Wq rounded+permuted
__device__ float g_wo[EMB * EMB];       // Wo rounded+permuted
__device__ float g_wk[HD * EMB];        // Wk rounded+permuted
__device__ float g_wv[HD * EMB];        // Wv rounded+permuted
__device__ float g_kvp[8 * T_SEQ * 128];// KV split-K partials

// ============================================================
// helpers
// ============================================================
__device__ __forceinline__ uint32_t smem_u32(const void* p) {
    uint32_t a;
    asm("{ .reg .u64 t; cvta.to.shared.u64 t, %1; cvt.u32.u64 %0, t; }" : "=r"(a) : "l"(p));
    return a;
}
__device__ __forceinline__ uint32_t f2tf32(float x) {
    uint32_t r;
    asm("cvt.rna.tf32.f32 %0, %1;" : "=r"(r) : "f"(x));
    return r;
}
__device__ __forceinline__ float rnd(float x) { return __uint_as_float(f2tf32(x)); }
__device__ __forceinline__ float fex2(float x) {
    float r;
    asm("ex2.approx.f32 %0, %1;" : "=f"(r) : "f"(x));
    return r;
}
__device__ __forceinline__ void cp16(uint32_t dst, const void* src) {
    asm volatile("cp.async.cg.shared.global [%0], [%1], 16;" :: "r"(dst), "l"(src) : "memory");
}
__device__ __forceinline__ void mma_tf32(float& d0, float& d1, float& d2, float& d3,
                                         uint32_t a0, uint32_t a1, uint32_t a2, uint32_t a3,
                                         uint32_t b0, uint32_t b1) {
    asm volatile("mma.sync.aligned.m16n8k8.row.col.f32.tf32.tf32.f32 "
                 "{%0,%1,%2,%3}, {%4,%5,%6,%7}, {%8,%9}, {%0,%1,%2,%3};"
                 : "+f"(d0), "+f"(d1), "+f"(d2), "+f"(d3)
                 : "r"(a0), "r"(a1), "r"(a2), "r"(a3), "r"(b0), "r"(b1));
}

// ============================================================
// fused round+permute prep pass.
// Per 8-float group along K: out[2j]=in[j], out[2j+1]=in[j+4].
// ============================================================
#define NG_BIG (T_SEQ * EMB / 8)
#define NG_W   (HD * EMB / 8)

__global__ void prep_pass(const float* __restrict__ x,  const float* __restrict__ wq,
                          const float* __restrict__ wo, const float* __restrict__ wk,
                          const float* __restrict__ wv,
                          float* __restrict__ xr,  float* __restrict__ wqr,
                          float* __restrict__ wor, float* __restrict__ wkr,
                          float* __restrict__ wvr) {
    const int total = 3 * NG_BIG + 2 * NG_W;
    for (int gi = blockIdx.x * blockDim.x + threadIdx.x; gi < total;
         gi += gridDim.x * blockDim.x) {
        const float* src; float* dst; int off;
        if (gi < NG_BIG)                { src = x;  dst = xr;  off = gi; }
        else if (gi < 2 * NG_BIG)       { src = wq; dst = wqr; off = gi - NG_BIG; }
        else if (gi < 3 * NG_BIG)       { src = wo; dst = wor; off = gi - 2 * NG_BIG; }
        else if (gi < 3 * NG_BIG + NG_W){ src = wk; dst = wkr; off = gi - 3 * NG_BIG; }
        else                            { src = wv; dst = wvr; off = gi - 3 * NG_BIG - NG_W; }
        float4 a = *(const float4*)(src + (size_t)off * 8);
        float4 b = *(const float4*)(src + (size_t)off * 8 + 4);
        float4 o0 = make_float4(rnd(a.x), rnd(b.x), rnd(a.y), rnd(b.y));
        float4 o1 = make_float4(rnd(a.z), rnd(b.z), rnd(a.w), rnd(b.w));
        *(float4*)(dst + (size_t)off * 8)     = o0;
        *(float4*)(dst + (size_t)off * 8 + 4) = o1;
    }
}

// ============================================================
// tf32 mma.sync GEMM on K-PERMUTED operands. LDS.64 fragments.
// mode 0: C[M,N]=A@B0^T, tiles over (bx=n, by=m).
// mode 2: split-K partial for KV proj. grid (8 ksplit, 16 m).
//         B rows 0-63=B0(Wk), 64-127=B1(Wv). Raw fp32 out, ldc=128,
//         partial p written at C + p*T*128.
// ============================================================
#define BKF 32
#define LDA 40
#define OPER_F (128 * LDA)                    // 5120 floats
#define GEMM_SMEM (2 * 2 * OPER_F * 4)        // 81920 bytes

__global__ __launch_bounds__(256, 2) void gemm_tf32mma(
    const float* __restrict__ A, const float* __restrict__ B0,
    const float* __restrict__ B1, float* __restrict__ C,
    int K, int N, int mode, int do_round, float oscale) {
    extern __shared__ float sm[];
    const int tid  = threadIdx.x;
    const int wid  = tid >> 5;
    const int lane = tid & 31;
    const int wm   = wid & 1;
    const int wn   = wid >> 1;
    const int m0   = blockIdx.y * 128;
    const int g    = lane >> 2;
    const int tig  = lane & 3;

    int n0, kbeg, NT;
    if (mode == 2) { n0 = 0; kbeg = blockIdx.x * 256; NT = 256 / BKF;
                     C += (size_t)blockIdx.x * T_SEQ * 128; }
    else           { n0 = blockIdx.x * 128; kbeg = 0; NT = K / BKF; }

    float acc[4][4][4];
#pragma unroll
    for (int i = 0; i < 4; i++)
#pragma unroll
        for (int j = 0; j < 4; j++)
#pragma unroll
            for (int r = 0; r < 4; r++) acc[i][j][r] = 0.f;

    auto stage = [&](int t, int b) {
        float* dstA = sm + b * 2 * OPER_F;
        float* dstB = dstA + OPER_F;
        const int kof = kbeg + t * BKF;
#pragma unroll
        for (int u = 0; u < 4; u++) {
            int idx = u * 256 + tid;
            int r = idx >> 3, c4 = idx & 7;
            cp16(smem_u32(dstA + r * LDA + c4 * 4),
                 A + (size_t)(m0 + r) * K + kof + c4 * 4);
            const float* gb;
            if (mode == 2) gb = (r < 64 ? B0 + (size_t)r * K : B1 + (size_t)(r - 64) * K)
                                + kof + c4 * 4;
            else           gb = B0 + (size_t)(n0 + r) * K + kof + c4 * 4;
            cp16(smem_u32(dstB + r * LDA + c4 * 4), gb);
        }
        asm volatile("cp.async.commit_group;" ::: "memory");
    };

    stage(0, 0);

    for (int t = 0; t < NT; t++) {
        if (t + 1 < NT) {
            stage(t + 1, (t + 1) & 1);
            asm volatile("cp.async.wait_group 1;" ::: "memory");
        } else {
            asm volatile("cp.async.wait_group 0;" ::: "memory");
        }
        __syncthreads();

        const float* sA = sm + (t & 1) * 2 * OPER_F + (wm * 64) * LDA;
        const float* sB = sm + (t & 1) * 2 * OPER_F + OPER_F + (wn * 32) * LDA;

#pragma unroll
        for (int ks = 0; ks < 4; ks++) {
            const int ko = ks * 8 + 2 * tig;
            uint32_t bf[4][2];
#pragma unroll
            for (int nt = 0; nt < 4; nt++) {
                float2 b = *(const float2*)(sB + (nt * 8 + g) * LDA + ko);
                bf[nt][0] = __float_as_uint(b.x);
                bf[nt][1] = __float_as_uint(b.y);
            }
            uint32_t af[4][4];
#pragma unroll
            for (int mt = 0; mt < 4; mt++) {
                float2 alo = *(const float2*)(sA + (mt * 16 + g) * LDA + ko);
                float2 ahi = *(const float2*)(sA + (mt * 16 + 8 + g) * LDA + ko);
                af[mt][0] = __float_as_uint(alo.x);
                af[mt][1] = __float_as_uint(ahi.x);
                af[mt][2] = __float_as_uint(alo.y);
                af[mt][3] = __float_as_uint(ahi.y);
            }
#pragma unroll
            for (int mt = 0; mt < 4; mt++)
#pragma unroll
                for (int nt = 0; nt < 4; nt++)
                    mma_tf32(acc[mt][nt][0], acc[mt][nt][1], acc[mt][nt][2], acc[mt][nt][3],
                             af[mt][0], af[mt][1], af[mt][2], af[mt][3],
                             bf[nt][0], bf[nt][1]);
        }
        __syncthreads();
    }

#pragma unroll
    for (int mt = 0; mt < 4; mt++) {
        const int row0 = m0 + wm * 64 + mt * 16 + g;
#pragma unroll
        for (int nt = 0; nt < 4; nt++) {
            float v0 = acc[mt][nt][0] * oscale, v1 = acc[mt][nt][1] * oscale;
            float v2 = acc[mt][nt][2] * oscale, v3 = acc[mt][nt][3] * oscale;
            if (do_round) { v0 = rnd(v0); v1 = rnd(v1); v2 = rnd(v2); v3 = rnd(v3); }
            const int colL = wn * 32 + nt * 8 + 2 * tig;
            if (mode == 2) {
                *(float2*)(C + (size_t)row0 * 128 + colL)       = make_float2(v0, v1);
                *(float2*)(C + (size_t)(row0 + 8) * 128 + colL) = make_float2(v2, v3);
            } else {
                const int col = n0 + colL;
                *(float2*)(C + (size_t)row0 * N + col)       = make_float2(v0, v1);
                *(float2*)(C + (size_t)(row0 + 8) * N + col) = make_float2(v2, v3);
            }
        }
    }
}

// ============================================================
// KV split-K reduce: sum 8 partials, round, split into K and V.
// ============================================================
__global__ void kv_reduce(const float* __restrict__ part,
                          float* __restrict__ Kd, float* __restrict__ Vd) {
    const int n4 = T_SEQ * 128 / 4;
    int idx = blockIdx.x * blockDim.x + threadIdx.x;
    if (idx >= n4) return;
    float4 s = *(const float4*)(part + (size_t)idx * 4);
#pragma unroll
    for (int p = 1; p < 8; p++) {
        float4 v = *(const float4*)(part + (size_t)p * T_SEQ * 128 + (size_t)idx * 4);
        s.x += v.x; s.y += v.y; s.z += v.z; s.w += v.w;
    }
    s.x = rnd(s.x); s.y = rnd(s.y); s.z = rnd(s.z); s.w = rnd(s.w);
    const int row = (idx * 4) >> 7;
    const int col = (idx * 4) & 127;
    if (col < 64) *(float4*)(Kd + (size_t)row * 64 + col)      = s;
    else          *(float4*)(Vd + (size_t)row * 64 + col - 64) = s;
}

// ============================================================
// Flash attention, mma.sync tf32, log2-domain softmax (R6
// buffering: single K/V buffer). Output A stored with K-permuted
// columns for the O-projection.
// ============================================================
#define SPK 68
#define SPV 72
#define SPP 68
#define ATT_SMEM ((64 * SPK + 64 * SPV + 128 * SPP) * 4)   // 70656 B

__global__ __launch_bounds__(256) void attn_mma(const float* __restrict__ Q,
                                                const float* __restrict__ Kg,
                                                const float* __restrict__ Vg,
                                                float* __restrict__ O) {
    extern __shared__ float sm[];
    float* Ksh = sm;
    float* Vsh = sm + 64 * SPK;
    float* P   = sm + 64 * SPK + 64 * SPV;

    const int h   = blockIdx.y;
    const int q0  = blockIdx.x * 128;
    const int tid = threadIdx.x;
    const int wid = tid >> 5;
    const int lane = tid & 31;
    const int g   = lane >> 2;
    const int tig = lane & 3;
    const float slope2 = exp2f(-0.25f * (float)(h + 1)) * LOG2E;

#pragma unroll
    for (int u = 0; u < 8; u++) {
        int idx = u * 256 + tid;
        int r = idx >> 4, c4 = idx & 15;
        *(float4*)(P + r * SPP + c4 * 4) =
            *(const float4*)(Q + (size_t)(q0 + r) * EMB + h * HD + c4 * 4);
    }
    __syncthreads();

    uint32_t qf[8][4];
    {
        const float* PW = P + wid * 16 * SPP;
#pragma unroll
        for (int ks = 0; ks < 8; ks++) {
            const int k = ks * 8 + tig;
            qf[ks][0] = __float_as_uint(PW[g * SPP + k]);
            qf[ks][1] = __float_as_uint(PW[(g + 8) * SPP + k]);
            qf[ks][2] = __float_as_uint(PW[g * SPP + k + 4]);
            qf[ks][3] = __float_as_uint(PW[(g + 8) * SPP + k + 4]);
        }
    }

    float oacc[8][4];
#pragma unroll
    for (int nt = 0; nt < 8; nt++)
#pragma unroll
        for (int r = 0; r < 4; r++) oacc[nt][r] = 0.f;

    float m0r = -1e30f, m1r = -1e30f;
    float l0 = 0.f, l1 = 0.f;
    const int i0 = q0 + wid * 16 + g;
    const int i1 = i0 + 8;
    float* PWm  = P + (wid * 16 + g) * SPP;
    float* PWm8 = PWm + 8 * SPP;

    for (int j0 = 0; j0 < q0 + 128; j0 += 64) {
        __syncthreads();
#pragma unroll
        for (int u = 0; u < 4; u++) {
            int idx = u * 256 + tid;
            int r = idx >> 4, c4 = idx & 15;
            cp16(smem_u32(Ksh + r * SPK + c4 * 4), Kg + (size_t)(j0 + r) * HD + c4 * 4);
            cp16(smem_u32(Vsh + r * SPV + c4 * 4), Vg + (size_t)(j0 + r) * HD + c4 * 4);
        }
        asm volatile("cp.async.commit_group;" ::: "memory");
        asm volatile("cp.async.wait_group 0;" ::: "memory");
        __syncthreads();

        float sacc[8][4];
#pragma unroll
        for (int nt = 0; nt < 8; nt++)
#pragma unroll
            for (int r = 0; r < 4; r++) sacc[nt][r] = 0.f;

#pragma unroll
        for (int ks = 0; ks < 8; ks++) {
#pragma unroll
            for (int nt = 0; nt < 8; nt++) {
                const float* kp = Ksh + (nt * 8 + g) * SPK + ks * 8 + tig;
                uint32_t b0 = __float_as_uint(kp[0]);
                uint32_t b1 = __float_as_uint(kp[4]);
                mma_tf32(sacc[nt][0], sacc[nt][1], sacc[nt][2], sacc[nt][3],
                         qf[ks][0], qf[ks][1], qf[ks][2], qf[ks][3], b0, b1);
            }
        }

        float mx0 = -1e30f, mx1 = -1e30f;
#pragma unroll
        for (int nt = 0; nt < 8; nt++) {
            const int jb = j0 + nt * 8 + 2 * tig;
            float v0 = (jb     <= i0) ? fmaf(slope2, (float)(jb     - i0), sacc[nt][0]) : -1e30f;
            float v1 = (jb + 1 <= i0) ? fmaf(slope2, (float)(jb + 1 - i0), sacc[nt][1]) : -1e30f;
            float v2 = (jb     <= i1) ? fmaf(slope2, (float)(jb     - i1), sacc[nt][2]) : -1e30f;
            float v3 = (jb + 1 <= i1) ? fmaf(slope2, (float)(jb + 1 - i1), sacc[nt][3]) : -1e30f;
            sacc[nt][0] = v0; sacc[nt][1] = v1; sacc[nt][2] = v2; sacc[nt][3] = v3;
            mx0 = fmaxf(mx0, fmaxf(v0, v1));
            mx1 = fmaxf(mx1, fmaxf(v2, v3));
        }
        mx0 = fmaxf(mx0, __shfl_xor_sync(0xffffffffu, mx0, 1));
        mx0 = fmaxf(mx0, __shfl_xor_sync(0xffffffffu, mx0, 2));
        mx1 = fmaxf(mx1, __shfl_xor_sync(0xffffffffu, mx1, 1));
        mx1 = fmaxf(mx1, __shfl_xor_sync(0xffffffffu, mx1, 2));

        const float mn0 = fmaxf(m0r, mx0);
        const float mn1 = fmaxf(m1r, mx1);
        const float a0 = fex2(m0r - mn0);
        const float a1 = fex2(m1r - mn1);

        float ps0 = 0.f, ps1 = 0.f;
#pragma unroll
        for (int nt = 0; nt < 8; nt++) {
            float e0 = fex2(sacc[nt][0] - mn0);
            float e1 = fex2(sacc[nt][1] - mn0);
            float e2 = fex2(sacc[nt][2] - mn1);
            float e3 = fex2(sacc[nt][3] - mn1);
            ps0 += e0 + e1;
            ps1 += e2 + e3;
            const int col = nt * 8 + 2 * tig;
            *(float2*)(PWm  + col) = make_float2(rnd(e0), rnd(e1));
            *(float2*)(PWm8 + col) = make_float2(rnd(e2), rnd(e3));
        }
        ps0 += __shfl_xor_sync(0xffffffffu, ps0, 1);
        ps0 += __shfl_xor_sync(0xffffffffu, ps0, 2);
        ps1 += __shfl_xor_sync(0xffffffffu, ps1, 1);
        ps1 += __shfl_xor_sync(0xffffffffu, ps1, 2);
        l0 = l0 * a0 + ps0;
        l1 = l1 * a1 + ps1;
#pragma unroll
        for (int nt = 0; nt < 8; nt++) {
            oacc[nt][0] *= a0; oacc[nt][1] *= a0;
            oacc[nt][2] *= a1; oacc[nt][3] *= a1;
        }
        m0r = mn0; m1r = mn1;
        __syncwarp();

        const float* PW = P + wid * 16 * SPP;
#pragma unroll
        for (int ks = 0; ks < 8; ks++) {
            const int k = ks * 8 + tig;
            uint32_t pa0 = __float_as_uint(PW[g * SPP + k]);
            uint32_t pa1 = __float_as_uint(PW[(g + 8) * SPP + k]);
            uint32_t pa2 = __float_as_uint(PW[g * SPP + k + 4]);
            uint32_t pa3 = __float_as_uint(PW[(g + 8) * SPP + k + 4]);
#pragma unroll
            for (int nt = 0; nt < 8; nt++) {
                const float* vp = Vsh + (ks * 8 + tig) * SPV + nt * 8 + g;
                uint32_t b0 = __float_as_uint(vp[0]);
                uint32_t b1 = __float_as_uint(vp[4 * SPV]);
                mma_tf32(oacc[nt][0], oacc[nt][1], oacc[nt][2], oacc[nt][3],
                         pa0, pa1, pa2, pa3, b0, b1);
            }
        }
    }

    // ---- normalize + store, K-PERMUTED columns for the O-proj ----
    // logical r in [0,8): stored at 2*(r%4) + r/4
    const int r0 = 2 * tig;
    const int r1 = 2 * tig + 1;
    const int p0 = 2 * (r0 & 3) + (r0 >> 2);
    const int p1 = 2 * (r1 & 3) + (r1 >> 2);
    const float inv0 = 1.0f / l0;
    const float inv1 = 1.0f / l1;
    const int row0 = q0 + wid * 16 + g;
#pragma unroll
    for (int nt = 0; nt < 8; nt++) {
        const int base = h * HD + nt * 8;
        O[(size_t)row0 * EMB + base + p0]       = rnd(oacc[nt][0] * inv0);
        O[(size_t)row0 * EMB + base + p1]       = rnd(oacc[nt][1] * inv0);
        O[(size_t)(row0 + 8) * EMB + base + p0] = rnd(oacc[nt][2] * inv1);
        O[(size_t)(row0 + 8) * EMB + base + p1] = rnd(oacc[nt][3] * inv1);
    }
}

// ============================================================
// launch
// ============================================================
extern "C" void kernel_launch(void* const* d_in, const int* in_sizes, int n_in,
                              void* d_out, int out_size) {
    (void)in_sizes; (void)n_in; (void)out_size;
    const float* x  = (const float*)d_in[0];
    const float* Wq = (const float*)d_in[1];
    const float* Wk = (const float*)d_in[2];
    const float* Wv = (const float*)d_in[3];
    const float* Wo = (const float*)d_in[4];
    float* out = (float*)d_out;

    void *pQ, *pK, *pV, *pA, *px, *pwq, *pwo, *pwk, *pwv, *pkvp;
    cudaGetSymbolAddress(&pQ, g_Q);
    cudaGetSymbolAddress(&pK, g_K);
    cudaGetSymbolAddress(&pV, g_V);
    cudaGetSymbolAddress(&pA, g_A);
    cudaGetSymbolAddress(&px, g_x);
    cudaGetSymbolAddress(&pwq, g_wq);
    cudaGetSymbolAddress(&pwo, g_wo);
    cudaGetSymbolAddress(&pwk, g_wk);
    cudaGetSymbolAddress(&pwv, g_wv);
    cudaGetSymbolAddress(&pkvp, g_kvp);
    float* Qd = (float*)pQ;   float* Kd = (float*)pK;
    float* Vd = (float*)pV;   float* Ad = (float*)pA;
    float* xr = (float*)px;   float* wqr = (float*)pwq;
    float* wor = (float*)pwo; float* wkr = (float*)pwk;
    float* wvr = (float*)pwv; float* kvp = (float*)pkvp;

    cudaFuncSetAttribute(gemm_tf32mma, cudaFuncAttributeMaxDynamicSharedMemorySize, GEMM_SMEM);
    cudaFuncSetAttribute(attn_mma, cudaFuncAttributeMaxDynamicSharedMemorySize, ATT_SMEM);

    // fused round + K-permute prep
    prep_pass<<<2048, 256>>>(x, Wq, Wo, Wk, Wv, xr, wqr, wor, wkr, wvr);

    // Q projection (round + scale by D^-1/2 * log2e)
    gemm_tf32mma<<<dim3(EMB / 128, T_SEQ / 128), 256, GEMM_SMEM>>>(
        xr, wqr, nullptr, Qd, EMB, EMB, 0, 1, 0.125f * LOG2E);
    // KV projection: split-K partials then reduce
    gemm_tf32mma<<<dim3(8, T_SEQ / 128), 256, GEMM_SMEM>>>(
        xr, wkr, wvr, kvp, EMB, 128, 2, 0, 1.0f);
    kv_reduce<<<(T_SEQ * 128 / 4 + 255) / 256, 256>>>(kvp, Kd, Vd);
    // attention
    attn_mma<<<dim3(T_SEQ / 128, NH), 256, ATT_SMEM>>>(Qd, Kd, Vd, Ad);
    // output projection
    gemm_tf32mma<<<dim3(EMB / 128, T_SEQ / 128), 256, GEMM_SMEM>>>(
        Ad, wor, nullptr, out, EMB, EMB, 0, 0, 1.0f);
}

// round 9
// speedup vs baseline: 1.3421x; 1.0189x over previous
#include <cuda_runtime.h>
#include <cstdint>

#define T_SEQ 2048
#define EMB   2048
#define NH    32
#define HD    64
#define LOG2E 1.4426950408889634f

// -------- scratch (device globals) --------
__device__ float g_Q[T_SEQ * EMB];      // q proj (scaled, rounded, D-permuted)
__device__ float g_K[T_SEQ * HD];       // k proj (rounded, D-permuted)
__device__ float g_V[HD * T_SEQ];       // v proj TRANSPOSED Vt[d][t], key-permuted
__device__ float g_A[T_SEQ * EMB];      // attention out (rounded, K-permuted cols)
__device__ float g_x [T_SEQ * EMB];     // x  rounded+permuted
__device__ float g_wq[EMB * EMB];       // Wq rounded+permuted
__device__ float g_wo[EMB * EMB];       // Wo rounded+permuted
__device__ float g_wk[HD * EMB];        // Wk rounded+permuted
__device__ float g_wv[HD * EMB];        // Wv rounded+permuted
__device__ float g_kvp[8 * T_SEQ * 128];// KV split-K partials

// ============================================================
// helpers
// ============================================================
__device__ __forceinline__ uint32_t smem_u32(const void* p) {
    uint32_t a;
    asm("{ .reg .u64 t; cvta.to.shared.u64 t, %1; cvt.u32.u64 %0, t; }" : "=r"(a) : "l"(p));
    return a;
}
__device__ __forceinline__ uint32_t f2tf32(float x) {
    uint32_t r;
    asm("cvt.rna.tf32.f32 %0, %1;" : "=r"(r) : "f"(x));
    return r;
}
__device__ __forceinline__ float rnd(float x) { return __uint_as_float(f2tf32(x)); }
__device__ __forceinline__ float fex2(float x) {
    float r;
    asm("ex2.approx.f32 %0, %1;" : "=f"(r) : "f"(x));
    return r;
}
__device__ __forceinline__ void cp16(uint32_t dst, const void* src) {
    asm volatile("cp.async.cg.shared.global [%0], [%1], 16;" :: "r"(dst), "l"(src) : "memory");
}
__device__ __forceinline__ void mma_tf32(float& d0, float& d1, float& d2, float& d3,
                                         uint32_t a0, uint32_t a1, uint32_t a2, uint32_t a3,
                                         uint32_t b0, uint32_t b1) {
    asm volatile("mma.sync.aligned.m16n8k8.row.col.f32.tf32.tf32.f32 "
                 "{%0,%1,%2,%3}, {%4,%5,%6,%7}, {%8,%9}, {%0,%1,%2,%3};"
                 : "+f"(d0), "+f"(d1), "+f"(d2), "+f"(d3)
                 : "r"(a0), "r"(a1), "r"(a2), "r"(a3), "r"(b0), "r"(b1));
}

// ============================================================
// fused round+permute prep: per 8-group out[2j]=in[j], out[2j+1]=in[j+4]
// ============================================================
#define NG_BIG (T_SEQ * EMB / 8)
#define NG_W   (HD * EMB / 8)

__global__ void prep_pass(const float* __restrict__ x,  const float* __restrict__ wq,
                          const float* __restrict__ wo, const float* __restrict__ wk,
                          const float* __restrict__ wv,
                          float* __restrict__ xr,  float* __restrict__ wqr,
                          float* __restrict__ wor, float* __restrict__ wkr,
                          float* __restrict__ wvr) {
    const int total = 3 * NG_BIG + 2 * NG_W;
    for (int gi = blockIdx.x * blockDim.x + threadIdx.x; gi < total;
         gi += gridDim.x * blockDim.x) {
        const float* src; float* dst; int off;
        if (gi < NG_BIG)                { src = x;  dst = xr;  off = gi; }
        else if (gi < 2 * NG_BIG)       { src = wq; dst = wqr; off = gi - NG_BIG; }
        else if (gi < 3 * NG_BIG)       { src = wo; dst = wor; off = gi - 2 * NG_BIG; }
        else if (gi < 3 * NG_BIG + NG_W){ src = wk; dst = wkr; off = gi - 3 * NG_BIG; }
        else                            { src = wv; dst = wvr; off = gi - 3 * NG_BIG - NG_W; }
        float4 a = *(const float4*)(src + (size_t)off * 8);
        float4 b = *(const float4*)(src + (size_t)off * 8 + 4);
        float4 o0 = make_float4(rnd(a.x), rnd(b.x), rnd(a.y), rnd(b.y));
        float4 o1 = make_float4(rnd(a.z), rnd(b.z), rnd(a.w), rnd(b.w));
        *(float4*)(dst + (size_t)off * 8)     = o0;
        *(float4*)(dst + (size_t)off * 8 + 4) = o1;
    }
}

// ============================================================
// tf32 mma.sync GEMM on K-permuted operands.
// mode 0: C[M,N] = A @ B0^T, grid (N/128, M/128).
// mode 3 (fused proj): 1D grid 384.
//   blocks <256 : Q-proj tile (perm+round epilogue, oscale 0.125*log2e)
//   blocks >=256: KV split-K partials (B1 rows<64, B2 rows>=64) -> C2
// ============================================================
#define BKF 32
#define LDA 40
#define OPER_F (128 * LDA)
#define GEMM_SMEM (2 * 2 * OPER_F * 4)        // 81920 bytes

__global__ __launch_bounds__(256, 2) void gemm_tf32mma(
    const float* __restrict__ A, const float* __restrict__ B0,
    const float* __restrict__ B1, const float* __restrict__ B2,
    float* __restrict__ C, float* __restrict__ C2,
    int K, int N, int mode) {
    extern __shared__ float sm[];
    const int tid  = threadIdx.x;
    const int wid  = tid >> 5;
    const int lane = tid & 31;
    const int wm   = wid & 1;
    const int wn   = wid >> 1;
    const int g    = lane >> 2;
    const int tig  = lane & 3;

    int role, m0, n0, kbeg, NT, do_round, do_perm;
    float oscale;
    float* Cout;
    if (mode == 3) {
        if (blockIdx.x < 256) {
            role = 0; do_perm = 1; do_round = 1; oscale = 0.125f * LOG2E;
            n0 = (blockIdx.x & 15) * 128; m0 = (blockIdx.x >> 4) * 128;
            kbeg = 0; NT = K / BKF; Cout = C;
        } else {
            role = 2; do_perm = 0; do_round = 0; oscale = 1.0f;
            const int b = blockIdx.x - 256;
            kbeg = (b & 7) * 256; m0 = (b >> 3) * 128; n0 = 0; NT = 256 / BKF;
            Cout = C2 + (size_t)(b & 7) * T_SEQ * 128;
        }
    } else {
        role = 0; do_perm = 0; do_round = 0; oscale = 1.0f;
        n0 = blockIdx.x * 128; m0 = blockIdx.y * 128;
        kbeg = 0; NT = K / BKF; Cout = C;
    }

    float acc[4][4][4];
#pragma unroll
    for (int i = 0; i < 4; i++)
#pragma unroll
        for (int j = 0; j < 4; j++)
#pragma unroll
            for (int r = 0; r < 4; r++) acc[i][j][r] = 0.f;

    auto stage = [&](int t, int b) {
        float* dstA = sm + b * 2 * OPER_F;
        float* dstB = dstA + OPER_F;
        const int kof = kbeg + t * BKF;
#pragma unroll
        for (int u = 0; u < 4; u++) {
            int idx = u * 256 + tid;
            int r = idx >> 3, c4 = idx & 7;
            cp16(smem_u32(dstA + r * LDA + c4 * 4),
                 A + (size_t)(m0 + r) * K + kof + c4 * 4);
            const float* gb;
            if (role == 2) gb = (r < 64 ? B1 + (size_t)r * K : B2 + (size_t)(r - 64) * K)
                                + kof + c4 * 4;
            else           gb = B0 + (size_t)(n0 + r) * K + kof + c4 * 4;
            cp16(smem_u32(dstB + r * LDA + c4 * 4), gb);
        }
        asm volatile("cp.async.commit_group;" ::: "memory");
    };

    stage(0, 0);

    for (int t = 0; t < NT; t++) {
        if (t + 1 < NT) {
            stage(t + 1, (t + 1) & 1);
            asm volatile("cp.async.wait_group 1;" ::: "memory");
        } else {
            asm volatile("cp.async.wait_group 0;" ::: "memory");
        }
        __syncthreads();

        const float* sA = sm + (t & 1) * 2 * OPER_F + (wm * 64) * LDA;
        const float* sB = sm + (t & 1) * 2 * OPER_F + OPER_F + (wn * 32) * LDA;

#pragma unroll
        for (int ks = 0; ks < 4; ks++) {
            const int ko = ks * 8 + 2 * tig;
            uint32_t bf[4][2];
#pragma unroll
            for (int nt = 0; nt < 4; nt++) {
                float2 b = *(const float2*)(sB + (nt * 8 + g) * LDA + ko);
                bf[nt][0] = __float_as_uint(b.x);
                bf[nt][1] = __float_as_uint(b.y);
            }
            uint32_t af[4][4];
#pragma unroll
            for (int mt = 0; mt < 4; mt++) {
                float2 alo = *(const float2*)(sA + (mt * 16 + g) * LDA + ko);
                float2 ahi = *(const float2*)(sA + (mt * 16 + 8 + g) * LDA + ko);
                af[mt][0] = __float_as_uint(alo.x);
                af[mt][1] = __float_as_uint(ahi.x);
                af[mt][2] = __float_as_uint(alo.y);
                af[mt][3] = __float_as_uint(ahi.y);
            }
#pragma unroll
            for (int mt = 0; mt < 4; mt++)
#pragma unroll
                for (int nt = 0; nt < 4; nt++)
                    mma_tf32(acc[mt][nt][0], acc[mt][nt][1], acc[mt][nt][2], acc[mt][nt][3],
                             af[mt][0], af[mt][1], af[mt][2], af[mt][3],
                             bf[nt][0], bf[nt][1]);
        }
        __syncthreads();
    }

    // epilogue
    const int cpa = 2 * ((2 * tig) & 3) + ((2 * tig) >> 2);       // perm8(2tig)
    const int cpb = 2 * ((2 * tig + 1) & 3) + ((2 * tig + 1) >> 2); // perm8(2tig+1)
#pragma unroll
    for (int mt = 0; mt < 4; mt++) {
        const int row0 = m0 + wm * 64 + mt * 16 + g;
#pragma unroll
        for (int nt = 0; nt < 4; nt++) {
            float v0 = acc[mt][nt][0] * oscale, v1 = acc[mt][nt][1] * oscale;
            float v2 = acc[mt][nt][2] * oscale, v3 = acc[mt][nt][3] * oscale;
            if (do_round) { v0 = rnd(v0); v1 = rnd(v1); v2 = rnd(v2); v3 = rnd(v3); }
            const int colL = wn * 32 + nt * 8;
            if (role == 2) {
                const int c = colL + 2 * tig;
                *(float2*)(Cout + (size_t)row0 * 128 + c)       = make_float2(v0, v1);
                *(float2*)(Cout + (size_t)(row0 + 8) * 128 + c) = make_float2(v2, v3);
            } else if (do_perm) {
                const int cb = n0 + colL;
                Cout[(size_t)row0 * N + cb + cpa]       = v0;
                Cout[(size_t)row0 * N + cb + cpb]       = v1;
                Cout[(size_t)(row0 + 8) * N + cb + cpa] = v2;
                Cout[(size_t)(row0 + 8) * N + cb + cpb] = v3;
            } else {
                const int col = n0 + colL + 2 * tig;
                *(float2*)(Cout + (size_t)row0 * N + col)       = make_float2(v0, v1);
                *(float2*)(Cout + (size_t)(row0 + 8) * N + col) = make_float2(v2, v3);
            }
        }
    }
}

// ============================================================
// KV reduce: sum 8 partials, round.
// K: [t][d] with d permuted within 8-groups.
// V: transposed Vt[d][t] with t permuted within 8-groups.
// ============================================================
__global__ void kv_reduce(const float* __restrict__ part,
                          float* __restrict__ Kd, float* __restrict__ Vt) {
    const int n4 = T_SEQ * 128 / 4;
    int idx = blockIdx.x * blockDim.x + threadIdx.x;
    if (idx >= n4) return;
    float4 s = *(const float4*)(part + (size_t)idx * 4);
#pragma unroll
    for (int p = 1; p < 8; p++) {
        float4 v = *(const float4*)(part + (size_t)p * T_SEQ * 128 + (size_t)idx * 4);
        s.x += v.x; s.y += v.y; s.z += v.z; s.w += v.w;
    }
    s.x = rnd(s.x); s.y = rnd(s.y); s.z = rnd(s.z); s.w = rnd(s.w);
    const int t = (idx * 4) >> 7;
    const int c = (idx * 4) & 127;
    if (c < 64) {
        // d-group permute: cols c..c+3 have j=(c&7)+i -> perm8(j)=2i + (c&4 ? 1 : 0)
        const int base = t * 64 + (c & ~7);
        const int o = (c & 4) ? 1 : 0;
        Kd[base + o + 0] = s.x;
        Kd[base + o + 2] = s.y;
        Kd[base + o + 4] = s.z;
        Kd[base + o + 6] = s.w;
    } else {
        const int d = c - 64;
        const int permt = (t & ~7) + 2 * (t & 3) + ((t >> 2) & 1);
        Vt[(size_t)(d + 0) * T_SEQ + permt] = s.x;
        Vt[(size_t)(d + 1) * T_SEQ + permt] = s.y;
        Vt[(size_t)(d + 2) * T_SEQ + permt] = s.z;
        Vt[(size_t)(d + 3) * T_SEQ + permt] = s.w;
    }
}

// ============================================================
// Flash attention, mma.sync tf32, log2-domain softmax.
// All fragment smem loads are LDS.64 via permuted layouts:
//   Q/K: D-dim permuted; P/Vt: key-dim permuted; V transposed.
// Largest q-tiles scheduled first.
// ============================================================
#define SPK 72
#define SPV 72
#define SPP 72
#define ATT_SMEM ((64 * SPK + 64 * SPV + 128 * SPP) * 4)   // 73728 B

__global__ __launch_bounds__(256) void attn_mma(const float* __restrict__ Q,
                                                const float* __restrict__ Kg,
                                                const float* __restrict__ Vt,
                                                float* __restrict__ O) {
    extern __shared__ float sm[];
    float* Ksh = sm;                        // [64 keys][SPK] (d permuted)
    float* Vsh = sm + 64 * SPK;             // [64 d][SPV]    (keys permuted)
    float* P   = sm + 64 * SPK + 64 * SPV;  // [128 q][SPP]

    const int h   = blockIdx.y;
    const int q0  = (gridDim.x - 1 - blockIdx.x) * 128;   // largest-first
    const int tid = threadIdx.x;
    const int wid = tid >> 5;
    const int lane = tid & 31;
    const int g   = lane >> 2;
    const int tig = lane & 3;
    const float slope2 = exp2f(-0.25f * (float)(h + 1)) * LOG2E;

    // stage Q tile (already scaled+rounded+D-permuted)
#pragma unroll
    for (int u = 0; u < 8; u++) {
        int idx = u * 256 + tid;
        int r = idx >> 4, c4 = idx & 15;
        *(float4*)(P + r * SPP + c4 * 4) =
            *(const float4*)(Q + (size_t)(q0 + r) * EMB + h * HD + c4 * 4);
    }
    __syncthreads();

    uint32_t qf[8][4];
    {
        const float* PW = P + wid * 16 * SPP;
#pragma unroll
        for (int ks = 0; ks < 8; ks++) {
            const int ko = ks * 8 + 2 * tig;
            float2 lo = *(const float2*)(PW + g * SPP + ko);
            float2 hi = *(const float2*)(PW + (g + 8) * SPP + ko);
            qf[ks][0] = __float_as_uint(lo.x);
            qf[ks][1] = __float_as_uint(hi.x);
            qf[ks][2] = __float_as_uint(lo.y);
            qf[ks][3] = __float_as_uint(hi.y);
        }
    }

    float oacc[8][4];
#pragma unroll
    for (int nt = 0; nt < 8; nt++)
#pragma unroll
        for (int r = 0; r < 4; r++) oacc[nt][r] = 0.f;

    float m0r = -1e30f, m1r = -1e30f;
    float l0 = 0.f, l1 = 0.f;
    const int i0 = q0 + wid * 16 + g;
    const int i1 = i0 + 8;
    float* PWm  = P + (wid * 16 + g) * SPP;
    float* PWm8 = PWm + 8 * SPP;
    // permuted store cols for P (logical 2tig, 2tig+1)
    const int cpa = 2 * ((2 * tig) & 3) + ((2 * tig) >> 2);
    const int cpb = 2 * ((2 * tig + 1) & 3) + ((2 * tig + 1) >> 2);

    for (int j0 = 0; j0 < q0 + 128; j0 += 64) {
        __syncthreads();
#pragma unroll
        for (int u = 0; u < 4; u++) {
            int idx = u * 256 + tid;
            int r = idx >> 4, c4 = idx & 15;
            cp16(smem_u32(Ksh + r * SPK + c4 * 4), Kg + (size_t)(j0 + r) * HD + c4 * 4);
            cp16(smem_u32(Vsh + r * SPV + c4 * 4), Vt + (size_t)r * T_SEQ + j0 + c4 * 4);
        }
        asm volatile("cp.async.commit_group;" ::: "memory");
        asm volatile("cp.async.wait_group 0;" ::: "memory");
        __syncthreads();

        // ---- S = Q @ K^T ----
        float sacc[8][4];
#pragma unroll
        for (int nt = 0; nt < 8; nt++)
#pragma unroll
            for (int r = 0; r < 4; r++) sacc[nt][r] = 0.f;

#pragma unroll
        for (int ks = 0; ks < 8; ks++) {
            const int ko = ks * 8 + 2 * tig;
#pragma unroll
            for (int nt = 0; nt < 8; nt++) {
                float2 b = *(const float2*)(Ksh + (nt * 8 + g) * SPK + ko);
                mma_tf32(sacc[nt][0], sacc[nt][1], sacc[nt][2], sacc[nt][3],
                         qf[ks][0], qf[ks][1], qf[ks][2], qf[ks][3],
                         __float_as_uint(b.x), __float_as_uint(b.y));
            }
        }

        // ---- ALiBi + causal mask, tile max ----
        float mx0 = -1e30f, mx1 = -1e30f;
#pragma unroll
        for (int nt = 0; nt < 8; nt++) {
            const int jb = j0 + nt * 8 + 2 * tig;
            float v0 = (jb     <= i0) ? fmaf(slope2, (float)(jb     - i0), sacc[nt][0]) : -1e30f;
            float v1 = (jb + 1 <= i0) ? fmaf(slope2, (float)(jb + 1 - i0), sacc[nt][1]) : -1e30f;
            float v2 = (jb     <= i1) ? fmaf(slope2, (float)(jb     - i1), sacc[nt][2]) : -1e30f;
            float v3 = (jb + 1 <= i1) ? fmaf(slope2, (float)(jb + 1 - i1), sacc[nt][3]) : -1e30f;
            sacc[nt][0] = v0; sacc[nt][1] = v1; sacc[nt][2] = v2; sacc[nt][3] = v3;
            mx0 = fmaxf(mx0, fmaxf(v0, v1));
            mx1 = fmaxf(mx1, fmaxf(v2, v3));
        }
        mx0 = fmaxf(mx0, __shfl_xor_sync(0xffffffffu, mx0, 1));
        mx0 = fmaxf(mx0, __shfl_xor_sync(0xffffffffu, mx0, 2));
        mx1 = fmaxf(mx1, __shfl_xor_sync(0xffffffffu, mx1, 1));
        mx1 = fmaxf(mx1, __shfl_xor_sync(0xffffffffu, mx1, 2));

        const float mn0 = fmaxf(m0r, mx0);
        const float mn1 = fmaxf(m1r, mx1);
        const float a0 = fex2(m0r - mn0);
        const float a1 = fex2(m1r - mn1);

        float ps0 = 0.f, ps1 = 0.f;
#pragma unroll
        for (int nt = 0; nt < 8; nt++) {
            float e0 = fex2(sacc[nt][0] - mn0);
            float e1 = fex2(sacc[nt][1] - mn0);
            float e2 = fex2(sacc[nt][2] - mn1);
            float e3 = fex2(sacc[nt][3] - mn1);
            ps0 += e0 + e1;
            ps1 += e2 + e3;
            const int cb = nt * 8;
            PWm [cb + cpa] = rnd(e0);
            PWm [cb + cpb] = rnd(e1);
            PWm8[cb + cpa] = rnd(e2);
            PWm8[cb + cpb] = rnd(e3);
        }
        ps0 += __shfl_xor_sync(0xffffffffu, ps0, 1);
        ps0 += __shfl_xor_sync(0xffffffffu, ps0, 2);
        ps1 += __shfl_xor_sync(0xffffffffu, ps1, 1);
        ps1 += __shfl_xor_sync(0xffffffffu, ps1, 2);
        l0 = l0 * a0 + ps0;
        l1 = l1 * a1 + ps1;
#pragma unroll
        for (int nt = 0; nt < 8; nt++) {
            oacc[nt][0] *= a0; oacc[nt][1] *= a0;
            oacc[nt][2] *= a1; oacc[nt][3] *= a1;
        }
        m0r = mn0; m1r = mn1;
        __syncwarp();

        // ---- O += P @ V  (A = P key-permuted, B = Vt key-permuted) ----
        const float* PW = P + wid * 16 * SPP;
#pragma unroll
        for (int ks = 0; ks < 8; ks++) {
            const int ko = ks * 8 + 2 * tig;
            float2 plo = *(const float2*)(PW + g * SPP + ko);
            float2 phi = *(const float2*)(PW + (g + 8) * SPP + ko);
            uint32_t pa0 = __float_as_uint(plo.x);
            uint32_t pa1 = __float_as_uint(phi.x);
            uint32_t pa2 = __float_as_uint(plo.y);
            uint32_t pa3 = __float_as_uint(phi.y);
#pragma unroll
            for (int nt = 0; nt < 8; nt++) {
                float2 b = *(const float2*)(Vsh + (nt * 8 + g) * SPV + ko);
                mma_tf32(oacc[nt][0], oacc[nt][1], oacc[nt][2], oacc[nt][3],
                         pa0, pa1, pa2, pa3,
                         __float_as_uint(b.x), __float_as_uint(b.y));
            }
        }
    }

    // ---- normalize + store, K-permuted columns for the O-proj ----
    const float inv0 = 1.0f / l0;
    const float inv1 = 1.0f / l1;
    const int row0 = q0 + wid * 16 + g;
#pragma unroll
    for (int nt = 0; nt < 8; nt++) {
        const int base = h * HD + nt * 8;
        O[(size_t)row0 * EMB + base + cpa]       = rnd(oacc[nt][0] * inv0);
        O[(size_t)row0 * EMB + base + cpb]       = rnd(oacc[nt][1] * inv0);
        O[(size_t)(row0 + 8) * EMB + base + cpa] = rnd(oacc[nt][2] * inv1);
        O[(size_t)(row0 + 8) * EMB + base + cpb] = rnd(oacc[nt][3] * inv1);
    }
}

// ============================================================
// launch
// ============================================================
extern "C" void kernel_launch(void* const* d_in, const int* in_sizes, int n_in,
                              void* d_out, int out_size) {
    (void)in_sizes; (void)n_in; (void)out_size;
    const float* x  = (const float*)d_in[0];
    const float* Wq = (const float*)d_in[1];
    const float* Wk = (const float*)d_in[2];
    const float* Wv = (const float*)d_in[3];
    const float* Wo = (const float*)d_in[4];
    float* out = (float*)d_out;

    void *pQ, *pK, *pV, *pA, *px, *pwq, *pwo, *pwk, *pwv, *pkvp;
    cudaGetSymbolAddress(&pQ, g_Q);
    cudaGetSymbolAddress(&pK, g_K);
    cudaGetSymbolAddress(&pV, g_V);
    cudaGetSymbolAddress(&pA, g_A);
    cudaGetSymbolAddress(&px, g_x);
    cudaGetSymbolAddress(&pwq, g_wq);
    cudaGetSymbolAddress(&pwo, g_wo);
    cudaGetSymbolAddress(&pwk, g_wk);
    cudaGetSymbolAddress(&pwv, g_wv);
    cudaGetSymbolAddress(&pkvp, g_kvp);
    float* Qd = (float*)pQ;   float* Kd = (float*)pK;
    float* Vd = (float*)pV;   float* Ad = (float*)pA;
    float* xr = (float*)px;   float* wqr = (float*)pwq;
    float* wor = (float*)pwo; float* wkr = (float*)pwk;
    float* wvr = (float*)pwv; float* kvp = (float*)pkvp;

    cudaFuncSetAttribute(gemm_tf32mma, cudaFuncAttributeMaxDynamicSharedMemorySize, GEMM_SMEM);
    cudaFuncSetAttribute(attn_mma, cudaFuncAttributeMaxDynamicSharedMemorySize, ATT_SMEM);

    // fused round + K-permute prep
    prep_pass<<<2048, 256>>>(x, Wq, Wo, Wk, Wv, xr, wqr, wor, wkr, wvr);

    // fused Q-proj + KV split-K partials (384 CTAs)
    gemm_tf32mma<<<384, 256, GEMM_SMEM>>>(
        xr, wqr, wkr, wvr, Qd, kvp, EMB, EMB, 3);
    kv_reduce<<<(T_SEQ * 128 / 4 + 255) / 256, 256>>>(kvp, Kd, Vd);
    // attention
    attn_mma<<<dim3(T_SEQ / 128, NH), 256, ATT_SMEM>>>(Qd, Kd, Vd, Ad);
    // output projection
    gemm_tf32mma<<<dim3(EMB / 128, T_SEQ / 128), 256, GEMM_SMEM>>>(
        Ad, wor, nullptr, nullptr, out, nullptr, EMB, EMB, 0);
}

// round 10
// speedup vs baseline: 1.4420x; 1.0744x over previous
#include <cuda_runtime.h>
#include <cstdint>

#define T_SEQ 2048
#define EMB   2048
#define NH    32
#define HD    64
#define LOG2E 1.4426950408889634f

// -------- scratch (device globals) --------
__device__ float g_Q[T_SEQ * EMB];      // q proj (scaled, rounded, D-permuted)
__device__ float g_K[T_SEQ * HD];       // k proj (rounded, D-permuted)
__device__ float g_V[HD * T_SEQ];       // v proj TRANSPOSED Vt[d][t], key-permuted
__device__ float g_A[T_SEQ * EMB];      // attention out (rounded, K-permuted cols)
__device__ float g_x [T_SEQ * EMB];     // x  rounded+permuted
__device__ float g_wq[EMB * EMB];       // Wq rounded+permuted
__device__ float g_wo[EMB * EMB];       // Wo rounded+permuted
__device__ float g_wk[HD * EMB];        // Wk rounded+permuted
__device__ float g_wv[HD * EMB];        // Wv rounded+permuted
__device__ float g_kvp[8 * T_SEQ * 128];// KV split-K partials

// ============================================================
// helpers
// ============================================================
__device__ __forceinline__ uint32_t smem_u32(const void* p) {
    uint32_t a;
    asm("{ .reg .u64 t; cvta.to.shared.u64 t, %1; cvt.u32.u64 %0, t; }" : "=r"(a) : "l"(p));
    return a;
}
__device__ __forceinline__ uint32_t f2tf32(float x) {
    uint32_t r;
    asm("cvt.rna.tf32.f32 %0, %1;" : "=r"(r) : "f"(x));
    return r;
}
__device__ __forceinline__ float rnd(float x) { return __uint_as_float(f2tf32(x)); }
__device__ __forceinline__ float fex2(float x) {
    float r;
    asm("ex2.approx.f32 %0, %1;" : "=f"(r) : "f"(x));
    return r;
}
__device__ __forceinline__ void cp16(uint32_t dst, const void* src) {
    asm volatile("cp.async.cg.shared.global [%0], [%1], 16;" :: "r"(dst), "l"(src) : "memory");
}
__device__ __forceinline__ void mma_tf32(float& d0, float& d1, float& d2, float& d3,
                                         uint32_t a0, uint32_t a1, uint32_t a2, uint32_t a3,
                                         uint32_t b0, uint32_t b1) {
    asm volatile("mma.sync.aligned.m16n8k8.row.col.f32.tf32.tf32.f32 "
                 "{%0,%1,%2,%3}, {%4,%5,%6,%7}, {%8,%9}, {%0,%1,%2,%3};"
                 : "+f"(d0), "+f"(d1), "+f"(d2), "+f"(d3)
                 : "r"(a0), "r"(a1), "r"(a2), "r"(a3), "r"(b0), "r"(b1));
}

// ============================================================
// fused round+permute prep: per 8-group out[2j]=in[j], out[2j+1]=in[j+4]
// ============================================================
#define NG_BIG (T_SEQ * EMB / 8)
#define NG_W   (HD * EMB / 8)

__global__ void prep_pass(const float* __restrict__ x,  const float* __restrict__ wq,
                          const float* __restrict__ wo, const float* __restrict__ wk,
                          const float* __restrict__ wv,
                          float* __restrict__ xr,  float* __restrict__ wqr,
                          float* __restrict__ wor, float* __restrict__ wkr,
                          float* __restrict__ wvr) {
    const int total = 3 * NG_BIG + 2 * NG_W;
    for (int gi = blockIdx.x * blockDim.x + threadIdx.x; gi < total;
         gi += gridDim.x * blockDim.x) {
        const float* src; float* dst; int off;
        if (gi < NG_BIG)                { src = x;  dst = xr;  off = gi; }
        else if (gi < 2 * NG_BIG)       { src = wq; dst = wqr; off = gi - NG_BIG; }
        else if (gi < 3 * NG_BIG)       { src = wo; dst = wor; off = gi - 2 * NG_BIG; }
        else if (gi < 3 * NG_BIG + NG_W){ src = wk; dst = wkr; off = gi - 3 * NG_BIG; }
        else                            { src = wv; dst = wvr; off = gi - 3 * NG_BIG - NG_W; }
        float4 a = *(const float4*)(src + (size_t)off * 8);
        float4 b = *(const float4*)(src + (size_t)off * 8 + 4);
        float4 o0 = make_float4(rnd(a.x), rnd(b.x), rnd(a.y), rnd(b.y));
        float4 o1 = make_float4(rnd(a.z), rnd(b.z), rnd(a.w), rnd(b.w));
        *(float4*)(dst + (size_t)off * 8)     = o0;
        *(float4*)(dst + (size_t)off * 8 + 4) = o1;
    }
}

// ============================================================
// tf32 mma.sync GEMM on K-permuted operands (unchanged from R9)
// ============================================================
#define BKF 32
#define LDA 40
#define OPER_F (128 * LDA)
#define GEMM_SMEM (2 * 2 * OPER_F * 4)        // 81920 bytes

__global__ __launch_bounds__(256, 2) void gemm_tf32mma(
    const float* __restrict__ A, const float* __restrict__ B0,
    const float* __restrict__ B1, const float* __restrict__ B2,
    float* __restrict__ C, float* __restrict__ C2,
    int K, int N, int mode) {
    extern __shared__ float sm[];
    const int tid  = threadIdx.x;
    const int wid  = tid >> 5;
    const int lane = tid & 31;
    const int wm   = wid & 1;
    const int wn   = wid >> 1;
    const int g    = lane >> 2;
    const int tig  = lane & 3;

    int role, m0, n0, kbeg, NT, do_round, do_perm;
    float oscale;
    float* Cout;
    if (mode == 3) {
        if (blockIdx.x < 256) {
            role = 0; do_perm = 1; do_round = 1; oscale = 0.125f * LOG2E;
            n0 = (blockIdx.x & 15) * 128; m0 = (blockIdx.x >> 4) * 128;
            kbeg = 0; NT = K / BKF; Cout = C;
        } else {
            role = 2; do_perm = 0; do_round = 0; oscale = 1.0f;
            const int b = blockIdx.x - 256;
            kbeg = (b & 7) * 256; m0 = (b >> 3) * 128; n0 = 0; NT = 256 / BKF;
            Cout = C2 + (size_t)(b & 7) * T_SEQ * 128;
        }
    } else {
        role = 0; do_perm = 0; do_round = 0; oscale = 1.0f;
        n0 = blockIdx.x * 128; m0 = blockIdx.y * 128;
        kbeg = 0; NT = K / BKF; Cout = C;
    }

    float acc[4][4][4];
#pragma unroll
    for (int i = 0; i < 4; i++)
#pragma unroll
        for (int j = 0; j < 4; j++)
#pragma unroll
            for (int r = 0; r < 4; r++) acc[i][j][r] = 0.f;

    auto stage = [&](int t, int b) {
        float* dstA = sm + b * 2 * OPER_F;
        float* dstB = dstA + OPER_F;
        const int kof = kbeg + t * BKF;
#pragma unroll
        for (int u = 0; u < 4; u++) {
            int idx = u * 256 + tid;
            int r = idx >> 3, c4 = idx & 7;
            cp16(smem_u32(dstA + r * LDA + c4 * 4),
                 A + (size_t)(m0 + r) * K + kof + c4 * 4);
            const float* gb;
            if (role == 2) gb = (r < 64 ? B1 + (size_t)r * K : B2 + (size_t)(r - 64) * K)
                                + kof + c4 * 4;
            else           gb = B0 + (size_t)(n0 + r) * K + kof + c4 * 4;
            cp16(smem_u32(dstB + r * LDA + c4 * 4), gb);
        }
        asm volatile("cp.async.commit_group;" ::: "memory");
    };

    stage(0, 0);

    for (int t = 0; t < NT; t++) {
        if (t + 1 < NT) {
            stage(t + 1, (t + 1) & 1);
            asm volatile("cp.async.wait_group 1;" ::: "memory");
        } else {
            asm volatile("cp.async.wait_group 0;" ::: "memory");
        }
        __syncthreads();

        const float* sA = sm + (t & 1) * 2 * OPER_F + (wm * 64) * LDA;
        const float* sB = sm + (t & 1) * 2 * OPER_F + OPER_F + (wn * 32) * LDA;

#pragma unroll
        for (int ks = 0; ks < 4; ks++) {
            const int ko = ks * 8 + 2 * tig;
            uint32_t bf[4][2];
#pragma unroll
            for (int nt = 0; nt < 4; nt++) {
                float2 b = *(const float2*)(sB + (nt * 8 + g) * LDA + ko);
                bf[nt][0] = __float_as_uint(b.x);
                bf[nt][1] = __float_as_uint(b.y);
            }
            uint32_t af[4][4];
#pragma unroll
            for (int mt = 0; mt < 4; mt++) {
                float2 alo = *(const float2*)(sA + (mt * 16 + g) * LDA + ko);
                float2 ahi = *(const float2*)(sA + (mt * 16 + 8 + g) * LDA + ko);
                af[mt][0] = __float_as_uint(alo.x);
                af[mt][1] = __float_as_uint(ahi.x);
                af[mt][2] = __float_as_uint(alo.y);
                af[mt][3] = __float_as_uint(ahi.y);
            }
#pragma unroll
            for (int mt = 0; mt < 4; mt++)
#pragma unroll
                for (int nt = 0; nt < 4; nt++)
                    mma_tf32(acc[mt][nt][0], acc[mt][nt][1], acc[mt][nt][2], acc[mt][nt][3],
                             af[mt][0], af[mt][1], af[mt][2], af[mt][3],
                             bf[nt][0], bf[nt][1]);
        }
        __syncthreads();
    }

    const int cpa = 2 * ((2 * tig) & 3) + ((2 * tig) >> 2);
    const int cpb = 2 * ((2 * tig + 1) & 3) + ((2 * tig + 1) >> 2);
#pragma unroll
    for (int mt = 0; mt < 4; mt++) {
        const int row0 = m0 + wm * 64 + mt * 16 + g;
#pragma unroll
        for (int nt = 0; nt < 4; nt++) {
            float v0 = acc[mt][nt][0] * oscale, v1 = acc[mt][nt][1] * oscale;
            float v2 = acc[mt][nt][2] * oscale, v3 = acc[mt][nt][3] * oscale;
            if (do_round) { v0 = rnd(v0); v1 = rnd(v1); v2 = rnd(v2); v3 = rnd(v3); }
            const int colL = wn * 32 + nt * 8;
            if (role == 2) {
                const int c = colL + 2 * tig;
                *(float2*)(Cout + (size_t)row0 * 128 + c)       = make_float2(v0, v1);
                *(float2*)(Cout + (size_t)(row0 + 8) * 128 + c) = make_float2(v2, v3);
            } else if (do_perm) {
                const int cb = n0 + colL;
                Cout[(size_t)row0 * N + cb + cpa]       = v0;
                Cout[(size_t)row0 * N + cb + cpb]       = v1;
                Cout[(size_t)(row0 + 8) * N + cb + cpa] = v2;
                Cout[(size_t)(row0 + 8) * N + cb + cpb] = v3;
            } else {
                const int col = n0 + colL + 2 * tig;
                *(float2*)(Cout + (size_t)row0 * N + col)       = make_float2(v0, v1);
                *(float2*)(Cout + (size_t)(row0 + 8) * N + col) = make_float2(v2, v3);
            }
        }
    }
}

// ============================================================
// KV reduce (unchanged from R9)
// ============================================================
__global__ void kv_reduce(const float* __restrict__ part,
                          float* __restrict__ Kd, float* __restrict__ Vt) {
    const int n4 = T_SEQ * 128 / 4;
    int idx = blockIdx.x * blockDim.x + threadIdx.x;
    if (idx >= n4) return;
    float4 s = *(const float4*)(part + (size_t)idx * 4);
#pragma unroll
    for (int p = 1; p < 8; p++) {
        float4 v = *(const float4*)(part + (size_t)p * T_SEQ * 128 + (size_t)idx * 4);
        s.x += v.x; s.y += v.y; s.z += v.z; s.w += v.w;
    }
    s.x = rnd(s.x); s.y = rnd(s.y); s.z = rnd(s.z); s.w = rnd(s.w);
    const int t = (idx * 4) >> 7;
    const int c = (idx * 4) & 127;
    if (c < 64) {
        const int base = t * 64 + (c & ~7);
        const int o = (c & 4) ? 1 : 0;
        Kd[base + o + 0] = s.x;
        Kd[base + o + 2] = s.y;
        Kd[base + o + 4] = s.z;
        Kd[base + o + 6] = s.w;
    } else {
        const int d = c - 64;
        const int permt = (t & ~7) + 2 * (t & 3) + ((t >> 2) & 1);
        Vt[(size_t)(d + 0) * T_SEQ + permt] = s.x;
        Vt[(size_t)(d + 1) * T_SEQ + permt] = s.y;
        Vt[(size_t)(d + 2) * T_SEQ + permt] = s.z;
        Vt[(size_t)(d + 3) * T_SEQ + permt] = s.w;
    }
}

// ============================================================
// Flash attention — 128-thread CTAs (4 warps, 64 q-rows) for
// 3 CTAs/SM occupancy. Same per-warp math as R9 (LDS.64
// permuted layouts, log2-domain softmax). Largest tiles first.
// ============================================================
#define SPK 72
#define SPV 72
#define SPP 72
#define QROWS 64
#define ATT_SMEM ((64 * SPK + 64 * SPV + QROWS * SPP) * 4)   // 55296 B

__global__ __launch_bounds__(128, 3) void attn_mma(const float* __restrict__ Q,
                                                   const float* __restrict__ Kg,
                                                   const float* __restrict__ Vt,
                                                   float* __restrict__ O) {
    extern __shared__ float sm[];
    float* Ksh = sm;                        // [64 keys][SPK] (d permuted)
    float* Vsh = sm + 64 * SPK;             // [64 d][SPV]    (keys permuted)
    float* P   = sm + 64 * SPK + 64 * SPV;  // [64 q][SPP]

    const int h   = blockIdx.y;
    const int q0  = (gridDim.x - 1 - blockIdx.x) * QROWS;   // largest-first
    const int tid = threadIdx.x;
    const int wid = tid >> 5;
    const int lane = tid & 31;
    const int g   = lane >> 2;
    const int tig = lane & 3;
    const float slope2 = exp2f(-0.25f * (float)(h + 1)) * LOG2E;

    // stage Q tile (scaled+rounded+D-permuted): 64 rows x 16 float4
#pragma unroll
    for (int u = 0; u < 8; u++) {
        int idx = u * 128 + tid;
        int r = idx >> 4, c4 = idx & 15;
        *(float4*)(P + r * SPP + c4 * 4) =
            *(const float4*)(Q + (size_t)(q0 + r) * EMB + h * HD + c4 * 4);
    }
    __syncthreads();

    uint32_t qf[8][4];
    {
        const float* PW = P + wid * 16 * SPP;
#pragma unroll
        for (int ks = 0; ks < 8; ks++) {
            const int ko = ks * 8 + 2 * tig;
            float2 lo = *(const float2*)(PW + g * SPP + ko);
            float2 hi = *(const float2*)(PW + (g + 8) * SPP + ko);
            qf[ks][0] = __float_as_uint(lo.x);
            qf[ks][1] = __float_as_uint(hi.x);
            qf[ks][2] = __float_as_uint(lo.y);
            qf[ks][3] = __float_as_uint(hi.y);
        }
    }

    float oacc[8][4];
#pragma unroll
    for (int nt = 0; nt < 8; nt++)
#pragma unroll
        for (int r = 0; r < 4; r++) oacc[nt][r] = 0.f;

    float m0r = -1e30f, m1r = -1e30f;
    float l0 = 0.f, l1 = 0.f;
    const int i0 = q0 + wid * 16 + g;
    const int i1 = i0 + 8;
    float* PWm  = P + (wid * 16 + g) * SPP;
    float* PWm8 = PWm + 8 * SPP;
    const int cpa = 2 * ((2 * tig) & 3) + ((2 * tig) >> 2);
    const int cpb = 2 * ((2 * tig + 1) & 3) + ((2 * tig + 1) >> 2);

    for (int j0 = 0; j0 < q0 + QROWS; j0 += 64) {
        __syncthreads();
        // stage K and Vt tiles: 64 rows x 16 float4 each; 128 threads
#pragma unroll
        for (int u = 0; u < 8; u++) {
            int idx = u * 128 + tid;
            int r = idx >> 4, c4 = idx & 15;
            cp16(smem_u32(Ksh + r * SPK + c4 * 4), Kg + (size_t)(j0 + r) * HD + c4 * 4);
            cp16(smem_u32(Vsh + r * SPV + c4 * 4), Vt + (size_t)r * T_SEQ + j0 + c4 * 4);
        }
        asm volatile("cp.async.commit_group;" ::: "memory");
        asm volatile("cp.async.wait_group 0;" ::: "memory");
        __syncthreads();

        // ---- S = Q @ K^T ----
        float sacc[8][4];
#pragma unroll
        for (int nt = 0; nt < 8; nt++)
#pragma unroll
            for (int r = 0; r < 4; r++) sacc[nt][r] = 0.f;

#pragma unroll
        for (int ks = 0; ks < 8; ks++) {
            const int ko = ks * 8 + 2 * tig;
#pragma unroll
            for (int nt = 0; nt < 8; nt++) {
                float2 b = *(const float2*)(Ksh + (nt * 8 + g) * SPK + ko);
                mma_tf32(sacc[nt][0], sacc[nt][1], sacc[nt][2], sacc[nt][3],
                         qf[ks][0], qf[ks][1], qf[ks][2], qf[ks][3],
                         __float_as_uint(b.x), __float_as_uint(b.y));
            }
        }

        // ---- ALiBi + causal mask, tile max ----
        float mx0 = -1e30f, mx1 = -1e30f;
#pragma unroll
        for (int nt = 0; nt < 8; nt++) {
            const int jb = j0 + nt * 8 + 2 * tig;
            float v0 = (jb     <= i0) ? fmaf(slope2, (float)(jb     - i0), sacc[nt][0]) : -1e30f;
            float v1 = (jb + 1 <= i0) ? fmaf(slope2, (float)(jb + 1 - i0), sacc[nt][1]) : -1e30f;
            float v2 = (jb     <= i1) ? fmaf(slope2, (float)(jb     - i1), sacc[nt][2]) : -1e30f;
            float v3 = (jb + 1 <= i1) ? fmaf(slope2, (float)(jb + 1 - i1), sacc[nt][3]) : -1e30f;
            sacc[nt][0] = v0; sacc[nt][1] = v1; sacc[nt][2] = v2; sacc[nt][3] = v3;
            mx0 = fmaxf(mx0, fmaxf(v0, v1));
            mx1 = fmaxf(mx1, fmaxf(v2, v3));
        }
        mx0 = fmaxf(mx0, __shfl_xor_sync(0xffffffffu, mx0, 1));
        mx0 = fmaxf(mx0, __shfl_xor_sync(0xffffffffu, mx0, 2));
        mx1 = fmaxf(mx1, __shfl_xor_sync(0xffffffffu, mx1, 1));
        mx1 = fmaxf(mx1, __shfl_xor_sync(0xffffffffu, mx1, 2));

        const float mn0 = fmaxf(m0r, mx0);
        const float mn1 = fmaxf(m1r, mx1);
        const float a0 = fex2(m0r - mn0);
        const float a1 = fex2(m1r - mn1);

        float ps0 = 0.f, ps1 = 0.f;
#pragma unroll
        for (int nt = 0; nt < 8; nt++) {
            float e0 = fex2(sacc[nt][0] - mn0);
            float e1 = fex2(sacc[nt][1] - mn0);
            float e2 = fex2(sacc[nt][2] - mn1);
            float e3 = fex2(sacc[nt][3] - mn1);
            ps0 += e0 + e1;
            ps1 += e2 + e3;
            const int cb = nt * 8;
            PWm [cb + cpa] = rnd(e0);
            PWm [cb + cpb] = rnd(e1);
            PWm8[cb + cpa] = rnd(e2);
            PWm8[cb + cpb] = rnd(e3);
        }
        ps0 += __shfl_xor_sync(0xffffffffu, ps0, 1);
        ps0 += __shfl_xor_sync(0xffffffffu, ps0, 2);
        ps1 += __shfl_xor_sync(0xffffffffu, ps1, 1);
        ps1 += __shfl_xor_sync(0xffffffffu, ps1, 2);
        l0 = l0 * a0 + ps0;
        l1 = l1 * a1 + ps1;
#pragma unroll
        for (int nt = 0; nt < 8; nt++) {
            oacc[nt][0] *= a0; oacc[nt][1] *= a0;
            oacc[nt][2] *= a1; oacc[nt][3] *= a1;
        }
        m0r = mn0; m1r = mn1;
        __syncwarp();

        // ---- O += P @ V ----
        const float* PW = P + wid * 16 * SPP;
#pragma unroll
        for (int ks = 0; ks < 8; ks++) {
            const int ko = ks * 8 + 2 * tig;
            float2 plo = *(const float2*)(PW + g * SPP + ko);
            float2 phi = *(const float2*)(PW + (g + 8) * SPP + ko);
            uint32_t pa0 = __float_as_uint(plo.x);
            uint32_t pa1 = __float_as_uint(phi.x);
            uint32_t pa2 = __float_as_uint(plo.y);
            uint32_t pa3 = __float_as_uint(phi.y);
#pragma unroll
            for (int nt = 0; nt < 8; nt++) {
                float2 b = *(const float2*)(Vsh + (nt * 8 + g) * SPV + ko);
                mma_tf32(oacc[nt][0], oacc[nt][1], oacc[nt][2], oacc[nt][3],
                         pa0, pa1, pa2, pa3,
                         __float_as_uint(b.x), __float_as_uint(b.y));
            }
        }
    }

    // ---- normalize + store, K-permuted columns for the O-proj ----
    const float inv0 = 1.0f / l0;
    const float inv1 = 1.0f / l1;
    const int row0 = q0 + wid * 16 + g;
#pragma unroll
    for (int nt = 0; nt < 8; nt++) {
        const int base = h * HD + nt * 8;
        O[(size_t)row0 * EMB + base + cpa]       = rnd(oacc[nt][0] * inv0);
        O[(size_t)row0 * EMB + base + cpb]       = rnd(oacc[nt][1] * inv0);
        O[(size_t)(row0 + 8) * EMB + base + cpa] = rnd(oacc[nt][2] * inv1);
        O[(size_t)(row0 + 8) * EMB + base + cpb] = rnd(oacc[nt][3] * inv1);
    }
}

// ============================================================
// launch
// ============================================================
extern "C" void kernel_launch(void* const* d_in, const int* in_sizes, int n_in,
                              void* d_out, int out_size) {
    (void)in_sizes; (void)n_in; (void)out_size;
    const float* x  = (const float*)d_in[0];
    const float* Wq = (const float*)d_in[1];
    const float* Wk = (const float*)d_in[2];
    const float* Wv = (const float*)d_in[3];
    const float* Wo = (const float*)d_in[4];
    float* out = (float*)d_out;

    void *pQ, *pK, *pV, *pA, *px, *pwq, *pwo, *pwk, *pwv, *pkvp;
    cudaGetSymbolAddress(&pQ, g_Q);
    cudaGetSymbolAddress(&pK, g_K);
    cudaGetSymbolAddress(&pV, g_V);
    cudaGetSymbolAddress(&pA, g_A);
    cudaGetSymbolAddress(&px, g_x);
    cudaGetSymbolAddress(&pwq, g_wq);
    cudaGetSymbolAddress(&pwo, g_wo);
    cudaGetSymbolAddress(&pwk, g_wk);
    cudaGetSymbolAddress(&pwv, g_wv);
    cudaGetSymbolAddress(&pkvp, g_kvp);
    float* Qd = (float*)pQ;   float* Kd = (float*)pK;
    float* Vd = (float*)pV;   float* Ad = (float*)pA;
    float* xr = (float*)px;   float* wqr = (float*)pwq;
    float* wor = (float*)pwo; float* wkr = (float*)pwk;
    float* wvr = (float*)pwv; float* kvp = (float*)pkvp;

    cudaFuncSetAttribute(gemm_tf32mma, cudaFuncAttributeMaxDynamicSharedMemorySize, GEMM_SMEM);
    cudaFuncSetAttribute(attn_mma, cudaFuncAttributeMaxDynamicSharedMemorySize, ATT_SMEM);

    prep_pass<<<2048, 256>>>(x, Wq, Wo, Wk, Wv, xr, wqr, wor, wkr, wvr);

    gemm_tf32mma<<<384, 256, GEMM_SMEM>>>(
        xr, wqr, wkr, wvr, Qd, kvp, EMB, EMB, 3);
    kv_reduce<<<(T_SEQ * 128 / 4 + 255) / 256, 256>>>(kvp, Kd, Vd);
    attn_mma<<<dim3(T_SEQ / QROWS, NH), 128, ATT_SMEM>>>(Qd, Kd, Vd, Ad);
    gemm_tf32mma<<<dim3(EMB / 128, T_SEQ / 128), 256, GEMM_SMEM>>>(
        Ad, wor, nullptr, nullptr, out, nullptr, EMB, EMB, 0);
}

// round 11
// speedup vs baseline: 1.5709x; 1.0894x over previous
#include <cuda_runtime.h>
#include <cstdint>

#define T_SEQ 2048
#define EMB   2048
#define NH    32
#define HD    64
#define LOG2E 1.4426950408889634f

// -------- scratch (device globals) --------
__device__ float g_Q[T_SEQ * EMB];      // q proj (scaled, rounded, D-permuted)
__device__ float g_K[T_SEQ * HD];       // k proj (rounded, D-permuted)
__device__ float g_V[HD * T_SEQ];       // v proj TRANSPOSED Vt[d][t], key-permuted
__device__ float g_A[T_SEQ * EMB];      // attention out (rounded, K-permuted cols)
__device__ float g_x [T_SEQ * EMB];     // x  rounded+permuted
__device__ float g_wq[EMB * EMB];       // Wq rounded+permuted
__device__ float g_wo[EMB * EMB];       // Wo rounded+permuted
__device__ float g_wk[HD * EMB];        // Wk rounded+permuted
__device__ float g_wv[HD * EMB];        // Wv rounded+permuted
__device__ float g_kvp[8 * T_SEQ * 128];// KV split-K partials

// ============================================================
// helpers
// ============================================================
__device__ __forceinline__ uint32_t smem_u32(const void* p) {
    uint32_t a;
    asm("{ .reg .u64 t; cvta.to.shared.u64 t, %1; cvt.u32.u64 %0, t; }" : "=r"(a) : "l"(p));
    return a;
}
__device__ __forceinline__ uint32_t f2tf32(float x) {
    uint32_t r;
    asm("cvt.rna.tf32.f32 %0, %1;" : "=r"(r) : "f"(x));
    return r;
}
__device__ __forceinline__ float rnd(float x) { return __uint_as_float(f2tf32(x)); }
__device__ __forceinline__ float fex2(float x) {
    float r;
    asm("ex2.approx.f32 %0, %1;" : "=f"(r) : "f"(x));
    return r;
}
__device__ __forceinline__ void cp16(uint32_t dst, const void* src) {
    asm volatile("cp.async.cg.shared.global [%0], [%1], 16;" :: "r"(dst), "l"(src) : "memory");
}
__device__ __forceinline__ void mma_tf32(float& d0, float& d1, float& d2, float& d3,
                                         uint32_t a0, uint32_t a1, uint32_t a2, uint32_t a3,
                                         uint32_t b0, uint32_t b1) {
    asm volatile("mma.sync.aligned.m16n8k8.row.col.f32.tf32.tf32.f32 "
                 "{%0,%1,%2,%3}, {%4,%5,%6,%7}, {%8,%9}, {%0,%1,%2,%3};"
                 : "+f"(d0), "+f"(d1), "+f"(d2), "+f"(d3)
                 : "r"(a0), "r"(a1), "r"(a2), "r"(a3), "r"(b0), "r"(b1));
}

// ============================================================
// fused round+permute prep: per 8-group out[2j]=in[j], out[2j+1]=in[j+4]
// ============================================================
#define NG_BIG (T_SEQ * EMB / 8)
#define NG_W   (HD * EMB / 8)

__global__ void prep_pass(const float* __restrict__ x,  const float* __restrict__ wq,
                          const float* __restrict__ wo, const float* __restrict__ wk,
                          const float* __restrict__ wv,
                          float* __restrict__ xr,  float* __restrict__ wqr,
                          float* __restrict__ wor, float* __restrict__ wkr,
                          float* __restrict__ wvr) {
    const int total = 3 * NG_BIG + 2 * NG_W;
    for (int gi = blockIdx.x * blockDim.x + threadIdx.x; gi < total;
         gi += gridDim.x * blockDim.x) {
        const float* src; float* dst; int off;
        if (gi < NG_BIG)                { src = x;  dst = xr;  off = gi; }
        else if (gi < 2 * NG_BIG)       { src = wq; dst = wqr; off = gi - NG_BIG; }
        else if (gi < 3 * NG_BIG)       { src = wo; dst = wor; off = gi - 2 * NG_BIG; }
        else if (gi < 3 * NG_BIG + NG_W){ src = wk; dst = wkr; off = gi - 3 * NG_BIG; }
        else                            { src = wv; dst = wvr; off = gi - 3 * NG_BIG - NG_W; }
        float4 a = *(const float4*)(src + (size_t)off * 8);
        float4 b = *(const float4*)(src + (size_t)off * 8 + 4);
        float4 o0 = make_float4(rnd(a.x), rnd(b.x), rnd(a.y), rnd(b.y));
        float4 o1 = make_float4(rnd(a.z), rnd(b.z), rnd(a.w), rnd(b.w));
        *(float4*)(dst + (size_t)off * 8)     = o0;
        *(float4*)(dst + (size_t)off * 8 + 4) = o1;
    }
}

// ============================================================
// tf32 mma.sync GEMM, K-permuted operands, 64x64 warp tiles.
// 128 threads (4 warps, 2x2), CTA tile 128x128, BK=32.
// mode 0: C = A @ B0^T, grid (N/128, M/128).
// mode 3: fused — blocks <256: Q-proj (perm+round, oscale);
//                 blocks >=256: KV split-K partials -> C2.
// ============================================================
#define BKF 32
#define LDA 40
#define OPER_F (128 * LDA)
#define GEMM_SMEM (2 * 2 * OPER_F * 4)        // 81920 bytes

__global__ __launch_bounds__(128, 2) void gemm_tf32mma(
    const float* __restrict__ A, const float* __restrict__ B0,
    const float* __restrict__ B1, const float* __restrict__ B2,
    float* __restrict__ C, float* __restrict__ C2,
    int K, int N, int mode) {
    extern __shared__ float sm[];
    const int tid  = threadIdx.x;
    const int wid  = tid >> 5;
    const int lane = tid & 31;
    const int wm   = wid & 1;          // row half (64 rows)
    const int wn   = wid >> 1;         // col half (64 cols)
    const int g    = lane >> 2;
    const int tig  = lane & 3;

    int role, m0, n0, kbeg, NT, do_round, do_perm;
    float oscale;
    float* Cout;
    if (mode == 3) {
        if (blockIdx.x < 256) {
            role = 0; do_perm = 1; do_round = 1; oscale = 0.125f * LOG2E;
            n0 = (blockIdx.x & 15) * 128; m0 = (blockIdx.x >> 4) * 128;
            kbeg = 0; NT = K / BKF; Cout = C;
        } else {
            role = 2; do_perm = 0; do_round = 0; oscale = 1.0f;
            const int b = blockIdx.x - 256;
            kbeg = (b & 7) * 256; m0 = (b >> 3) * 128; n0 = 0; NT = 256 / BKF;
            Cout = C2 + (size_t)(b & 7) * T_SEQ * 128;
        }
    } else {
        role = 0; do_perm = 0; do_round = 0; oscale = 1.0f;
        n0 = blockIdx.x * 128; m0 = blockIdx.y * 128;
        kbeg = 0; NT = K / BKF; Cout = C;
    }

    float acc[4][8][4];
#pragma unroll
    for (int i = 0; i < 4; i++)
#pragma unroll
        for (int j = 0; j < 8; j++)
#pragma unroll
            for (int r = 0; r < 4; r++) acc[i][j][r] = 0.f;

    auto stage = [&](int t, int b) {
        float* dstA = sm + b * 2 * OPER_F;
        float* dstB = dstA + OPER_F;
        const int kof = kbeg + t * BKF;
#pragma unroll
        for (int u = 0; u < 8; u++) {
            int idx = u * 128 + tid;          // 0..1023 float4 slots
            int r = idx >> 3, c4 = idx & 7;
            cp16(smem_u32(dstA + r * LDA + c4 * 4),
                 A + (size_t)(m0 + r) * K + kof + c4 * 4);
            const float* gb;
            if (role == 2) gb = (r < 64 ? B1 + (size_t)r * K : B2 + (size_t)(r - 64) * K)
                                + kof + c4 * 4;
            else           gb = B0 + (size_t)(n0 + r) * K + kof + c4 * 4;
            cp16(smem_u32(dstB + r * LDA + c4 * 4), gb);
        }
        asm volatile("cp.async.commit_group;" ::: "memory");
    };

    stage(0, 0);

    for (int t = 0; t < NT; t++) {
        if (t + 1 < NT) {
            stage(t + 1, (t + 1) & 1);
            asm volatile("cp.async.wait_group 1;" ::: "memory");
        } else {
            asm volatile("cp.async.wait_group 0;" ::: "memory");
        }
        __syncthreads();

        const float* sA = sm + (t & 1) * 2 * OPER_F + (wm * 64) * LDA;
        const float* sB = sm + (t & 1) * 2 * OPER_F + OPER_F + (wn * 64) * LDA;

#pragma unroll
        for (int ks = 0; ks < 4; ks++) {
            const int ko = ks * 8 + 2 * tig;
            uint32_t bf[8][2];
#pragma unroll
            for (int nt = 0; nt < 8; nt++) {
                float2 b = *(const float2*)(sB + (nt * 8 + g) * LDA + ko);
                bf[nt][0] = __float_as_uint(b.x);
                bf[nt][1] = __float_as_uint(b.y);
            }
            uint32_t af[4][4];
#pragma unroll
            for (int mt = 0; mt < 4; mt++) {
                float2 alo = *(const float2*)(sA + (mt * 16 + g) * LDA + ko);
                float2 ahi = *(const float2*)(sA + (mt * 16 + 8 + g) * LDA + ko);
                af[mt][0] = __float_as_uint(alo.x);
                af[mt][1] = __float_as_uint(ahi.x);
                af[mt][2] = __float_as_uint(alo.y);
                af[mt][3] = __float_as_uint(ahi.y);
            }
#pragma unroll
            for (int mt = 0; mt < 4; mt++)
#pragma unroll
                for (int nt = 0; nt < 8; nt++)
                    mma_tf32(acc[mt][nt][0], acc[mt][nt][1], acc[mt][nt][2], acc[mt][nt][3],
                             af[mt][0], af[mt][1], af[mt][2], af[mt][3],
                             bf[nt][0], bf[nt][1]);
        }
        __syncthreads();
    }

    const int cpa = 2 * ((2 * tig) & 3) + ((2 * tig) >> 2);
    const int cpb = 2 * ((2 * tig + 1) & 3) + ((2 * tig + 1) >> 2);
#pragma unroll
    for (int mt = 0; mt < 4; mt++) {
        const int row0 = m0 + wm * 64 + mt * 16 + g;
#pragma unroll
        for (int nt = 0; nt < 8; nt++) {
            float v0 = acc[mt][nt][0] * oscale, v1 = acc[mt][nt][1] * oscale;
            float v2 = acc[mt][nt][2] * oscale, v3 = acc[mt][nt][3] * oscale;
            if (do_round) { v0 = rnd(v0); v1 = rnd(v1); v2 = rnd(v2); v3 = rnd(v3); }
            const int colL = wn * 64 + nt * 8;
            if (role == 2) {
                const int c = colL + 2 * tig;
                *(float2*)(Cout + (size_t)row0 * 128 + c)       = make_float2(v0, v1);
                *(float2*)(Cout + (size_t)(row0 + 8) * 128 + c) = make_float2(v2, v3);
            } else if (do_perm) {
                const int cb = n0 + colL;
                Cout[(size_t)row0 * N + cb + cpa]       = v0;
                Cout[(size_t)row0 * N + cb + cpb]       = v1;
                Cout[(size_t)(row0 + 8) * N + cb + cpa] = v2;
                Cout[(size_t)(row0 + 8) * N + cb + cpb] = v3;
            } else {
                const int col = n0 + colL + 2 * tig;
                *(float2*)(Cout + (size_t)row0 * N + col)       = make_float2(v0, v1);
                *(float2*)(Cout + (size_t)(row0 + 8) * N + col) = make_float2(v2, v3);
            }
        }
    }
}

// ============================================================
// KV reduce (unchanged)
// ============================================================
__global__ void kv_reduce(const float* __restrict__ part,
                          float* __restrict__ Kd, float* __restrict__ Vt) {
    const int n4 = T_SEQ * 128 / 4;
    int idx = blockIdx.x * blockDim.x + threadIdx.x;
    if (idx >= n4) return;
    float4 s = *(const float4*)(part + (size_t)idx * 4);
#pragma unroll
    for (int p = 1; p < 8; p++) {
        float4 v = *(const float4*)(part + (size_t)p * T_SEQ * 128 + (size_t)idx * 4);
        s.x += v.x; s.y += v.y; s.z += v.z; s.w += v.w;
    }
    s.x = rnd(s.x); s.y = rnd(s.y); s.z = rnd(s.z); s.w = rnd(s.w);
    const int t = (idx * 4) >> 7;
    const int c = (idx * 4) & 127;
    if (c < 64) {
        const int base = t * 64 + (c & ~7);
        const int o = (c & 4) ? 1 : 0;
        Kd[base + o + 0] = s.x;
        Kd[base + o + 2] = s.y;
        Kd[base + o + 4] = s.z;
        Kd[base + o + 6] = s.w;
    } else {
        const int d = c - 64;
        const int permt = (t & ~7) + 2 * (t & 3) + ((t >> 2) & 1);
        Vt[(size_t)(d + 0) * T_SEQ + permt] = s.x;
        Vt[(size_t)(d + 1) * T_SEQ + permt] = s.y;
        Vt[(size_t)(d + 2) * T_SEQ + permt] = s.z;
        Vt[(size_t)(d + 3) * T_SEQ + permt] = s.w;
    }
}

// ============================================================
// Flash attention (unchanged from R10): 128-thread CTAs,
// LDS.64 permuted layouts, log2-domain softmax, largest-first.
// ============================================================
#define SPK 72
#define SPV 72
#define SPP 72
#define QROWS 64
#define ATT_SMEM ((64 * SPK + 64 * SPV + QROWS * SPP) * 4)   // 55296 B

__global__ __launch_bounds__(128, 3) void attn_mma(const float* __restrict__ Q,
                                                   const float* __restrict__ Kg,
                                                   const float* __restrict__ Vt,
                                                   float* __restrict__ O) {
    extern __shared__ float sm[];
    float* Ksh = sm;
    float* Vsh = sm + 64 * SPK;
    float* P   = sm + 64 * SPK + 64 * SPV;

    const int h   = blockIdx.y;
    const int q0  = (gridDim.x - 1 - blockIdx.x) * QROWS;
    const int tid = threadIdx.x;
    const int wid = tid >> 5;
    const int lane = tid & 31;
    const int g   = lane >> 2;
    const int tig = lane & 3;
    const float slope2 = exp2f(-0.25f * (float)(h + 1)) * LOG2E;

#pragma unroll
    for (int u = 0; u < 8; u++) {
        int idx = u * 128 + tid;
        int r = idx >> 4, c4 = idx & 15;
        *(float4*)(P + r * SPP + c4 * 4) =
            *(const float4*)(Q + (size_t)(q0 + r) * EMB + h * HD + c4 * 4);
    }
    __syncthreads();

    uint32_t qf[8][4];
    {
        const float* PW = P + wid * 16 * SPP;
#pragma unroll
        for (int ks = 0; ks < 8; ks++) {
            const int ko = ks * 8 + 2 * tig;
            float2 lo = *(const float2*)(PW + g * SPP + ko);
            float2 hi = *(const float2*)(PW + (g + 8) * SPP + ko);
            qf[ks][0] = __float_as_uint(lo.x);
            qf[ks][1] = __float_as_uint(hi.x);
            qf[ks][2] = __float_as_uint(lo.y);
            qf[ks][3] = __float_as_uint(hi.y);
        }
    }

    float oacc[8][4];
#pragma unroll
    for (int nt = 0; nt < 8; nt++)
#pragma unroll
        for (int r = 0; r < 4; r++) oacc[nt][r] = 0.f;

    float m0r = -1e30f, m1r = -1e30f;
    float l0 = 0.f, l1 = 0.f;
    const int i0 = q0 + wid * 16 + g;
    const int i1 = i0 + 8;
    float* PWm  = P + (wid * 16 + g) * SPP;
    float* PWm8 = PWm + 8 * SPP;
    const int cpa = 2 * ((2 * tig) & 3) + ((2 * tig) >> 2);
    const int cpb = 2 * ((2 * tig + 1) & 3) + ((2 * tig + 1) >> 2);

    for (int j0 = 0; j0 < q0 + QROWS; j0 += 64) {
        __syncthreads();
#pragma unroll
        for (int u = 0; u < 8; u++) {
            int idx = u * 128 + tid;
            int r = idx >> 4, c4 = idx & 15;
            cp16(smem_u32(Ksh + r * SPK + c4 * 4), Kg + (size_t)(j0 + r) * HD + c4 * 4);
            cp16(smem_u32(Vsh + r * SPV + c4 * 4), Vt + (size_t)r * T_SEQ + j0 + c4 * 4);
        }
        asm volatile("cp.async.commit_group;" ::: "memory");
        asm volatile("cp.async.wait_group 0;" ::: "memory");
        __syncthreads();

        float sacc[8][4];
#pragma unroll
        for (int nt = 0; nt < 8; nt++)
#pragma unroll
            for (int r = 0; r < 4; r++) sacc[nt][r] = 0.f;

#pragma unroll
        for (int ks = 0; ks < 8; ks++) {
            const int ko = ks * 8 + 2 * tig;
#pragma unroll
            for (int nt = 0; nt < 8; nt++) {
                float2 b = *(const float2*)(Ksh + (nt * 8 + g) * SPK + ko);
                mma_tf32(sacc[nt][0], sacc[nt][1], sacc[nt][2], sacc[nt][3],
                         qf[ks][0], qf[ks][1], qf[ks][2], qf[ks][3],
                         __float_as_uint(b.x), __float_as_uint(b.y));
            }
        }

        float mx0 = -1e30f, mx1 = -1e30f;
#pragma unroll
        for (int nt = 0; nt < 8; nt++) {
            const int jb = j0 + nt * 8 + 2 * tig;
            float v0 = (jb     <= i0) ? fmaf(slope2, (float)(jb     - i0), sacc[nt][0]) : -1e30f;
            float v1 = (jb + 1 <= i0) ? fmaf(slope2, (float)(jb + 1 - i0), sacc[nt][1]) : -1e30f;
            float v2 = (jb     <= i1) ? fmaf(slope2, (float)(jb     - i1), sacc[nt][2]) : -1e30f;
            float v3 = (jb + 1 <= i1) ? fmaf(slope2, (float)(jb + 1 - i1), sacc[nt][3]) : -1e30f;
            sacc[nt][0] = v0; sacc[nt][1] = v1; sacc[nt][2] = v2; sacc[nt][3] = v3;
            mx0 = fmaxf(mx0, fmaxf(v0, v1));
            mx1 = fmaxf(mx1, fmaxf(v2, v3));
        }
        mx0 = fmaxf(mx0, __shfl_xor_sync(0xffffffffu, mx0, 1));
        mx0 = fmaxf(mx0, __shfl_xor_sync(0xffffffffu, mx0, 2));
        mx1 = fmaxf(mx1, __shfl_xor_sync(0xffffffffu, mx1, 1));
        mx1 = fmaxf(mx1, __shfl_xor_sync(0xffffffffu, mx1, 2));

        const float mn0 = fmaxf(m0r, mx0);
        const float mn1 = fmaxf(m1r, mx1);
        const float a0 = fex2(m0r - mn0);
        const float a1 = fex2(m1r - mn1);

        float ps0 = 0.f, ps1 = 0.f;
#pragma unroll
        for (int nt = 0; nt < 8; nt++) {
            float e0 = fex2(sacc[nt][0] - mn0);
            float e1 = fex2(sacc[nt][1] - mn0);
            float e2 = fex2(sacc[nt][2] - mn1);
            float e3 = fex2(sacc[nt][3] - mn1);
            ps0 += e0 + e1;
            ps1 += e2 + e3;
            const int cb = nt * 8;
            PWm [cb + cpa] = rnd(e0);
            PWm [cb + cpb] = rnd(e1);
            PWm8[cb + cpa] = rnd(e2);
            PWm8[cb + cpb] = rnd(e3);
        }
        ps0 += __shfl_xor_sync(0xffffffffu, ps0, 1);
        ps0 += __shfl_xor_sync(0xffffffffu, ps0, 2);
        ps1 += __shfl_xor_sync(0xffffffffu, ps1, 1);
        ps1 += __shfl_xor_sync(0xffffffffu, ps1, 2);
        l0 = l0 * a0 + ps0;
        l1 = l1 * a1 + ps1;
#pragma unroll
        for (int nt = 0; nt < 8; nt++) {
            oacc[nt][0] *= a0; oacc[nt][1] *= a0;
            oacc[nt][2] *= a1; oacc[nt][3] *= a1;
        }
        m0r = mn0; m1r = mn1;
        __syncwarp();

        const float* PW = P + wid * 16 * SPP;
#pragma unroll
        for (int ks = 0; ks < 8; ks++) {
            const int ko = ks * 8 + 2 * tig;
            float2 plo = *(const float2*)(PW + g * SPP + ko);
            float2 phi = *(const float2*)(PW + (g + 8) * SPP + ko);
            uint32_t pa0 = __float_as_uint(plo.x);
            uint32_t pa1 = __float_as_uint(phi.x);
            uint32_t pa2 = __float_as_uint(plo.y);
            uint32_t pa3 = __float_as_uint(phi.y);
#pragma unroll
            for (int nt = 0; nt < 8; nt++) {
                float2 b = *(const float2*)(Vsh + (nt * 8 + g) * SPV + ko);
                mma_tf32(oacc[nt][0], oacc[nt][1], oacc[nt][2], oacc[nt][3],
                         pa0, pa1, pa2, pa3,
                         __float_as_uint(b.x), __float_as_uint(b.y));
            }
        }
    }

    const float inv0 = 1.0f / l0;
    const float inv1 = 1.0f / l1;
    const int row0 = q0 + wid * 16 + g;
#pragma unroll
    for (int nt = 0; nt < 8; nt++) {
        const int base = h * HD + nt * 8;
        O[(size_t)row0 * EMB + base + cpa]       = rnd(oacc[nt][0] * inv0);
        O[(size_t)row0 * EMB + base + cpb]       = rnd(oacc[nt][1] * inv0);
        O[(size_t)(row0 + 8) * EMB + base + cpa] = rnd(oacc[nt][2] * inv1);
        O[(size_t)(row0 + 8) * EMB + base + cpb] = rnd(oacc[nt][3] * inv1);
    }
}

// ============================================================
// launch
// ============================================================
extern "C" void kernel_launch(void* const* d_in, const int* in_sizes, int n_in,
                              void* d_out, int out_size) {
    (void)in_sizes; (void)n_in; (void)out_size;
    const float* x  = (const float*)d_in[0];
    const float* Wq = (const float*)d_in[1];
    const float* Wk = (const float*)d_in[2];
    const float* Wv = (const float*)d_in[3];
    const float* Wo = (const float*)d_in[4];
    float* out = (float*)d_out;

    void *pQ, *pK, *pV, *pA, *px, *pwq, *pwo, *pwk, *pwv, *pkvp;
    cudaGetSymbolAddress(&pQ, g_Q);
    cudaGetSymbolAddress(&pK, g_K);
    cudaGetSymbolAddress(&pV, g_V);
    cudaGetSymbolAddress(&pA, g_A);
    cudaGetSymbolAddress(&px, g_x);
    cudaGetSymbolAddress(&pwq, g_wq);
    cudaGetSymbolAddress(&pwo, g_wo);
    cudaGetSymbolAddress(&pwk, g_wk);
    cudaGetSymbolAddress(&pwv, g_wv);
    cudaGetSymbolAddress(&pkvp, g_kvp);
    float* Qd = (float*)pQ;   float* Kd = (float*)pK;
    float* Vd = (float*)pV;   float* Ad = (float*)pA;
    float* xr = (float*)px;   float* wqr = (float*)pwq;
    float* wor = (float*)pwo; float* wkr = (float*)pwk;
    float* wvr = (float*)pwv; float* kvp = (float*)pkvp;

    cudaFuncSetAttribute(gemm_tf32mma, cudaFuncAttributeMaxDynamicSharedMemorySize, GEMM_SMEM);
    cudaFuncSetAttribute(attn_mma, cudaFuncAttributeMaxDynamicSharedMemorySize, ATT_SMEM);

    prep_pass<<<2048, 256>>>(x, Wq, Wo, Wk, Wv, xr, wqr, wor, wkr, wvr);

    gemm_tf32mma<<<384, 128, GEMM_SMEM>>>(
        xr, wqr, wkr, wvr, Qd, kvp, EMB, EMB, 3);
    kv_reduce<<<(T_SEQ * 128 / 4 + 255) / 256, 256>>>(kvp, Kd, Vd);
    attn_mma<<<dim3(T_SEQ / QROWS, NH), 128, ATT_SMEM>>>(Qd, Kd, Vd, Ad);
    gemm_tf32mma<<<dim3(EMB / 128, T_SEQ / 128), 128, GEMM_SMEM>>>(
        Ad, wor, nullptr, nullptr, out, nullptr, EMB, EMB, 0);
}

// round 12
// speedup vs baseline: 1.5905x; 1.0125x over previous
#include <cuda_runtime.h>
#include <cstdint>

#define T_SEQ 2048
#define EMB   2048
#define NH    32
#define HD    64
#define LOG2E 1.4426950408889634f

// -------- scratch (device globals) --------
__device__ float g_Q[T_SEQ * EMB];      // q proj (scaled, rounded, D-permuted)
__device__ float g_K[T_SEQ * HD];       // k proj (rounded, D-permuted)
__device__ float g_V[HD * T_SEQ];       // v proj TRANSPOSED Vt[d][t], key-permuted
__device__ float g_A[T_SEQ * EMB];      // attention out (rounded, K-permuted cols)
__device__ float g_x [T_SEQ * EMB];     // x  rounded+permuted
__device__ float g_wq[EMB * EMB];       // Wq rounded+permuted
__device__ float g_wo[EMB * EMB];       // Wo rounded+permuted
__device__ float g_wk[HD * EMB];        // Wk rounded+permuted
__device__ float g_wv[HD * EMB];        // Wv rounded+permuted
__device__ float g_kvp[8 * T_SEQ * 128];// KV split-K partials

// ============================================================
// helpers
// ============================================================
__device__ __forceinline__ uint32_t smem_u32(const void* p) {
    uint32_t a;
    asm("{ .reg .u64 t; cvta.to.shared.u64 t, %1; cvt.u32.u64 %0, t; }" : "=r"(a) : "l"(p));
    return a;
}
__device__ __forceinline__ uint32_t f2tf32(float x) {
    uint32_t r;
    asm("cvt.rna.tf32.f32 %0, %1;" : "=r"(r) : "f"(x));
    return r;
}
__device__ __forceinline__ float rnd(float x) { return __uint_as_float(f2tf32(x)); }
__device__ __forceinline__ float fex2(float x) {
    float r;
    asm("ex2.approx.f32 %0, %1;" : "=f"(r) : "f"(x));
    return r;
}
__device__ __forceinline__ void cp16(uint32_t dst, const void* src) {
    asm volatile("cp.async.cg.shared.global [%0], [%1], 16;" :: "r"(dst), "l"(src) : "memory");
}
__device__ __forceinline__ void mma_tf32(float& d0, float& d1, float& d2, float& d3,
                                         uint32_t a0, uint32_t a1, uint32_t a2, uint32_t a3,
                                         uint32_t b0, uint32_t b1) {
    asm volatile("mma.sync.aligned.m16n8k8.row.col.f32.tf32.tf32.f32 "
                 "{%0,%1,%2,%3}, {%4,%5,%6,%7}, {%8,%9}, {%0,%1,%2,%3};"
                 : "+f"(d0), "+f"(d1), "+f"(d2), "+f"(d3)
                 : "r"(a0), "r"(a1), "r"(a2), "r"(a3), "r"(b0), "r"(b1));
}

// ============================================================
// fused round+permute prep: per 8-group out[2j]=in[j], out[2j+1]=in[j+4]
// ============================================================
#define NG_BIG (T_SEQ * EMB / 8)
#define NG_W   (HD * EMB / 8)

__global__ void prep_pass(const float* __restrict__ x,  const float* __restrict__ wq,
                          const float* __restrict__ wo, const float* __restrict__ wk,
                          const float* __restrict__ wv,
                          float* __restrict__ xr,  float* __restrict__ wqr,
                          float* __restrict__ wor, float* __restrict__ wkr,
                          float* __restrict__ wvr) {
    const int total = 3 * NG_BIG + 2 * NG_W;
    for (int gi = blockIdx.x * blockDim.x + threadIdx.x; gi < total;
         gi += gridDim.x * blockDim.x) {
        const float* src; float* dst; int off;
        if (gi < NG_BIG)                { src = x;  dst = xr;  off = gi; }
        else if (gi < 2 * NG_BIG)       { src = wq; dst = wqr; off = gi - NG_BIG; }
        else if (gi < 3 * NG_BIG)       { src = wo; dst = wor; off = gi - 2 * NG_BIG; }
        else if (gi < 3 * NG_BIG + NG_W){ src = wk; dst = wkr; off = gi - 3 * NG_BIG; }
        else                            { src = wv; dst = wvr; off = gi - 3 * NG_BIG - NG_W; }
        float4 a = *(const float4*)(src + (size_t)off * 8);
        float4 b = *(const float4*)(src + (size_t)off * 8 + 4);
        float4 o0 = make_float4(rnd(a.x), rnd(b.x), rnd(a.y), rnd(b.y));
        float4 o1 = make_float4(rnd(a.z), rnd(b.z), rnd(a.w), rnd(b.w));
        *(float4*)(dst + (size_t)off * 8)     = o0;
        *(float4*)(dst + (size_t)off * 8 + 4) = o1;
    }
}

// ============================================================
// tf32 mma.sync GEMM, K-permuted operands, 64x64 warp tiles.
// (unchanged from R11)
// ============================================================
#define BKF 32
#define LDA 40
#define OPER_F (128 * LDA)
#define GEMM_SMEM (2 * 2 * OPER_F * 4)        // 81920 bytes

__global__ __launch_bounds__(128, 2) void gemm_tf32mma(
    const float* __restrict__ A, const float* __restrict__ B0,
    const float* __restrict__ B1, const float* __restrict__ B2,
    float* __restrict__ C, float* __restrict__ C2,
    int K, int N, int mode) {
    extern __shared__ float sm[];
    const int tid  = threadIdx.x;
    const int wid  = tid >> 5;
    const int lane = tid & 31;
    const int wm   = wid & 1;
    const int wn   = wid >> 1;
    const int g    = lane >> 2;
    const int tig  = lane & 3;

    int role, m0, n0, kbeg, NT, do_round, do_perm;
    float oscale;
    float* Cout;
    if (mode == 3) {
        if (blockIdx.x < 256) {
            role = 0; do_perm = 1; do_round = 1; oscale = 0.125f * LOG2E;
            n0 = (blockIdx.x & 15) * 128; m0 = (blockIdx.x >> 4) * 128;
            kbeg = 0; NT = K / BKF; Cout = C;
        } else {
            role = 2; do_perm = 0; do_round = 0; oscale = 1.0f;
            const int b = blockIdx.x - 256;
            kbeg = (b & 7) * 256; m0 = (b >> 3) * 128; n0 = 0; NT = 256 / BKF;
            Cout = C2 + (size_t)(b & 7) * T_SEQ * 128;
        }
    } else {
        role = 0; do_perm = 0; do_round = 0; oscale = 1.0f;
        n0 = blockIdx.x * 128; m0 = blockIdx.y * 128;
        kbeg = 0; NT = K / BKF; Cout = C;
    }

    float acc[4][8][4];
#pragma unroll
    for (int i = 0; i < 4; i++)
#pragma unroll
        for (int j = 0; j < 8; j++)
#pragma unroll
            for (int r = 0; r < 4; r++) acc[i][j][r] = 0.f;

    auto stage = [&](int t, int b) {
        float* dstA = sm + b * 2 * OPER_F;
        float* dstB = dstA + OPER_F;
        const int kof = kbeg + t * BKF;
#pragma unroll
        for (int u = 0; u < 8; u++) {
            int idx = u * 128 + tid;
            int r = idx >> 3, c4 = idx & 7;
            cp16(smem_u32(dstA + r * LDA + c4 * 4),
                 A + (size_t)(m0 + r) * K + kof + c4 * 4);
            const float* gb;
            if (role == 2) gb = (r < 64 ? B1 + (size_t)r * K : B2 + (size_t)(r - 64) * K)
                                + kof + c4 * 4;
            else           gb = B0 + (size_t)(n0 + r) * K + kof + c4 * 4;
            cp16(smem_u32(dstB + r * LDA + c4 * 4), gb);
        }
        asm volatile("cp.async.commit_group;" ::: "memory");
    };

    stage(0, 0);

    for (int t = 0; t < NT; t++) {
        if (t + 1 < NT) {
            stage(t + 1, (t + 1) & 1);
            asm volatile("cp.async.wait_group 1;" ::: "memory");
        } else {
            asm volatile("cp.async.wait_group 0;" ::: "memory");
        }
        __syncthreads();

        const float* sA = sm + (t & 1) * 2 * OPER_F + (wm * 64) * LDA;
        const float* sB = sm + (t & 1) * 2 * OPER_F + OPER_F + (wn * 64) * LDA;

#pragma unroll
        for (int ks = 0; ks < 4; ks++) {
            const int ko = ks * 8 + 2 * tig;
            uint32_t bf[8][2];
#pragma unroll
            for (int nt = 0; nt < 8; nt++) {
                float2 b = *(const float2*)(sB + (nt * 8 + g) * LDA + ko);
                bf[nt][0] = __float_as_uint(b.x);
                bf[nt][1] = __float_as_uint(b.y);
            }
            uint32_t af[4][4];
#pragma unroll
            for (int mt = 0; mt < 4; mt++) {
                float2 alo = *(const float2*)(sA + (mt * 16 + g) * LDA + ko);
                float2 ahi = *(const float2*)(sA + (mt * 16 + 8 + g) * LDA + ko);
                af[mt][0] = __float_as_uint(alo.x);
                af[mt][1] = __float_as_uint(ahi.x);
                af[mt][2] = __float_as_uint(alo.y);
                af[mt][3] = __float_as_uint(ahi.y);
            }
#pragma unroll
            for (int mt = 0; mt < 4; mt++)
#pragma unroll
                for (int nt = 0; nt < 8; nt++)
                    mma_tf32(acc[mt][nt][0], acc[mt][nt][1], acc[mt][nt][2], acc[mt][nt][3],
                             af[mt][0], af[mt][1], af[mt][2], af[mt][3],
                             bf[nt][0], bf[nt][1]);
        }
        __syncthreads();
    }

    const int cpa = 2 * ((2 * tig) & 3) + ((2 * tig) >> 2);
    const int cpb = 2 * ((2 * tig + 1) & 3) + ((2 * tig + 1) >> 2);
#pragma unroll
    for (int mt = 0; mt < 4; mt++) {
        const int row0 = m0 + wm * 64 + mt * 16 + g;
#pragma unroll
        for (int nt = 0; nt < 8; nt++) {
            float v0 = acc[mt][nt][0] * oscale, v1 = acc[mt][nt][1] * oscale;
            float v2 = acc[mt][nt][2] * oscale, v3 = acc[mt][nt][3] * oscale;
            if (do_round) { v0 = rnd(v0); v1 = rnd(v1); v2 = rnd(v2); v3 = rnd(v3); }
            const int colL = wn * 64 + nt * 8;
            if (role == 2) {
                const int c = colL + 2 * tig;
                *(float2*)(Cout + (size_t)row0 * 128 + c)       = make_float2(v0, v1);
                *(float2*)(Cout + (size_t)(row0 + 8) * 128 + c) = make_float2(v2, v3);
            } else if (do_perm) {
                const int cb = n0 + colL;
                Cout[(size_t)row0 * N + cb + cpa]       = v0;
                Cout[(size_t)row0 * N + cb + cpb]       = v1;
                Cout[(size_t)(row0 + 8) * N + cb + cpa] = v2;
                Cout[(size_t)(row0 + 8) * N + cb + cpb] = v3;
            } else {
                const int col = n0 + colL + 2 * tig;
                *(float2*)(Cout + (size_t)row0 * N + col)       = make_float2(v0, v1);
                *(float2*)(Cout + (size_t)(row0 + 8) * N + col) = make_float2(v2, v3);
            }
        }
    }
}

// ============================================================
// KV reduce (unchanged)
// ============================================================
__global__ void kv_reduce(const float* __restrict__ part,
                          float* __restrict__ Kd, float* __restrict__ Vt) {
    const int n4 = T_SEQ * 128 / 4;
    int idx = blockIdx.x * blockDim.x + threadIdx.x;
    if (idx >= n4) return;
    float4 s = *(const float4*)(part + (size_t)idx * 4);
#pragma unroll
    for (int p = 1; p < 8; p++) {
        float4 v = *(const float4*)(part + (size_t)p * T_SEQ * 128 + (size_t)idx * 4);
        s.x += v.x; s.y += v.y; s.z += v.z; s.w += v.w;
    }
    s.x = rnd(s.x); s.y = rnd(s.y); s.z = rnd(s.z); s.w = rnd(s.w);
    const int t = (idx * 4) >> 7;
    const int c = (idx * 4) & 127;
    if (c < 64) {
        const int base = t * 64 + (c & ~7);
        const int o = (c & 4) ? 1 : 0;
        Kd[base + o + 0] = s.x;
        Kd[base + o + 2] = s.y;
        Kd[base + o + 4] = s.z;
        Kd[base + o + 6] = s.w;
    } else {
        const int d = c - 64;
        const int permt = (t & ~7) + 2 * (t & 3) + ((t >> 2) & 1);
        Vt[(size_t)(d + 0) * T_SEQ + permt] = s.x;
        Vt[(size_t)(d + 1) * T_SEQ + permt] = s.y;
        Vt[(size_t)(d + 2) * T_SEQ + permt] = s.z;
        Vt[(size_t)(d + 3) * T_SEQ + permt] = s.w;
    }
}

// ============================================================
// Flash attention — 32-key tiles, 3 smem buffers, ONE barrier
// per tile (cp.async prefetch pipelined under compute).
// 128-thread CTAs, LDS.64 permuted layouts, log2 softmax.
// smem: K 3x[32][72], V 3x[64][40], P [64][40] = 68608 B.
// ============================================================
#define SPK 72
#define SPV 40
#define SPP 40
#define TKEY 32
#define KBUF (TKEY * SPK)          // 2304 floats
#define VBUF (64 * SPV)            // 2560 floats
#define QROWS 64
#define ATT_SMEM ((3 * KBUF + 3 * VBUF + QROWS * SPP) * 4)   // 68608 B

__global__ __launch_bounds__(128, 3) void attn_mma(const float* __restrict__ Q,
                                                   const float* __restrict__ Kg,
                                                   const float* __restrict__ Vt,
                                                   float* __restrict__ O) {
    extern __shared__ float sm[];
    float* Kbase = sm;                       // 3 x [32][SPK]
    float* Vbase = sm + 3 * KBUF;            // 3 x [64][SPV]
    float* P     = sm + 3 * KBUF + 3 * VBUF; // [64][SPP]

    const int h   = blockIdx.y;
    const int q0  = (gridDim.x - 1 - blockIdx.x) * QROWS;   // largest-first
    const int tid = threadIdx.x;
    const int wid = tid >> 5;
    const int lane = tid & 31;
    const int g   = lane >> 2;
    const int tig = lane & 3;
    const float slope2 = exp2f(-0.25f * (float)(h + 1)) * LOG2E;

    // ---- stage Q (scaled/rounded/D-permuted) into K-buffer region ----
    // 64 rows x 64 floats, stride SPK (region holds 3*2304 >= 64*72)
#pragma unroll
    for (int u = 0; u < 8; u++) {
        int idx = u * 128 + tid;
        int r = idx >> 4, c4 = idx & 15;
        *(float4*)(Kbase + r * SPK + c4 * 4) =
            *(const float4*)(Q + (size_t)(q0 + r) * EMB + h * HD + c4 * 4);
    }
    __syncthreads();

    uint32_t qf[8][4];
    {
        const float* QW = Kbase + wid * 16 * SPK;
#pragma unroll
        for (int ks = 0; ks < 8; ks++) {
            const int ko = ks * 8 + 2 * tig;
            float2 lo = *(const float2*)(QW + g * SPK + ko);
            float2 hi = *(const float2*)(QW + (g + 8) * SPK + ko);
            qf[ks][0] = __float_as_uint(lo.x);
            qf[ks][1] = __float_as_uint(hi.x);
            qf[ks][2] = __float_as_uint(lo.y);
            qf[ks][3] = __float_as_uint(hi.y);
        }
    }
    __syncthreads();   // all warps read Q before prefetch overwrites

    // ---- prefetch helper: tile t -> buffer t%3 ----
    auto prefetch = [&](int t) {
        const int b = t % 3;
        const int j0 = t * TKEY;
        float* Kb = Kbase + b * KBUF;
        float* Vb = Vbase + b * VBUF;
#pragma unroll
        for (int u = 0; u < 4; u++) {
            int idx = u * 128 + tid;
            // K: 32 rows x 16 float4
            int kr = idx >> 4, kc = idx & 15;
            cp16(smem_u32(Kb + kr * SPK + kc * 4), Kg + (size_t)(j0 + kr) * HD + kc * 4);
            // V: 64 rows x 8 float4
            int vr = idx >> 3, vc = idx & 7;
            cp16(smem_u32(Vb + vr * SPV + vc * 4), Vt + (size_t)vr * T_SEQ + j0 + vc * 4);
        }
        asm volatile("cp.async.commit_group;" ::: "memory");
    };

    float oacc[8][4];
#pragma unroll
    for (int nt = 0; nt < 8; nt++)
#pragma unroll
        for (int r = 0; r < 4; r++) oacc[nt][r] = 0.f;

    float m0r = -1e30f, m1r = -1e30f;
    float l0 = 0.f, l1 = 0.f;
    const int i0 = q0 + wid * 16 + g;
    const int i1 = i0 + 8;
    float* PWm  = P + (wid * 16 + g) * SPP;
    float* PWm8 = PWm + 8 * SPP;
    const int cpa = 2 * ((2 * tig) & 3) + ((2 * tig) >> 2);
    const int cpb = 2 * ((2 * tig + 1) & 3) + ((2 * tig + 1) >> 2);

    const int NTILE = (q0 + QROWS) / TKEY;
    prefetch(0);

    for (int t = 0; t < NTILE; t++) {
        const int j0 = t * TKEY;
        if (t + 1 < NTILE) {
            prefetch(t + 1);    // buffer (t+1)%3: disjoint from t and t-1
            asm volatile("cp.async.wait_group 1;" ::: "memory");
        } else {
            asm volatile("cp.async.wait_group 0;" ::: "memory");
        }
        __syncthreads();        // tile t visible to all; closes compute(t-1)

        const float* Ksh = Kbase + (t % 3) * KBUF;
        const float* Vsh = Vbase + (t % 3) * VBUF;

        // ---- S = Q @ K^T (32 keys) ----
        float sacc[4][4];
#pragma unroll
        for (int nt = 0; nt < 4; nt++)
#pragma unroll
            for (int r = 0; r < 4; r++) sacc[nt][r] = 0.f;

#pragma unroll
        for (int ks = 0; ks < 8; ks++) {
            const int ko = ks * 8 + 2 * tig;
#pragma unroll
            for (int nt = 0; nt < 4; nt++) {
                float2 b = *(const float2*)(Ksh + (nt * 8 + g) * SPK + ko);
                mma_tf32(sacc[nt][0], sacc[nt][1], sacc[nt][2], sacc[nt][3],
                         qf[ks][0], qf[ks][1], qf[ks][2], qf[ks][3],
                         __float_as_uint(b.x), __float_as_uint(b.y));
            }
        }

        // ---- ALiBi + causal mask, tile max ----
        float mx0 = -1e30f, mx1 = -1e30f;
#pragma unroll
        for (int nt = 0; nt < 4; nt++) {
            const int jb = j0 + nt * 8 + 2 * tig;
            float v0 = (jb     <= i0) ? fmaf(slope2, (float)(jb     - i0), sacc[nt][0]) : -1e30f;
            float v1 = (jb + 1 <= i0) ? fmaf(slope2, (float)(jb + 1 - i0), sacc[nt][1]) : -1e30f;
            float v2 = (jb     <= i1) ? fmaf(slope2, (float)(jb     - i1), sacc[nt][2]) : -1e30f;
            float v3 = (jb + 1 <= i1) ? fmaf(slope2, (float)(jb + 1 - i1), sacc[nt][3]) : -1e30f;
            sacc[nt][0] = v0; sacc[nt][1] = v1; sacc[nt][2] = v2; sacc[nt][3] = v3;
            mx0 = fmaxf(mx0, fmaxf(v0, v1));
            mx1 = fmaxf(mx1, fmaxf(v2, v3));
        }
        mx0 = fmaxf(mx0, __shfl_xor_sync(0xffffffffu, mx0, 1));
        mx0 = fmaxf(mx0, __shfl_xor_sync(0xffffffffu, mx0, 2));
        mx1 = fmaxf(mx1, __shfl_xor_sync(0xffffffffu, mx1, 1));
        mx1 = fmaxf(mx1, __shfl_xor_sync(0xffffffffu, mx1, 2));

        const float mn0 = fmaxf(m0r, mx0);
        const float mn1 = fmaxf(m1r, mx1);
        const float a0 = fex2(m0r - mn0);
        const float a1 = fex2(m1r - mn1);

        float ps0 = 0.f, ps1 = 0.f;
#pragma unroll
        for (int nt = 0; nt < 4; nt++) {
            float e0 = fex2(sacc[nt][0] - mn0);
            float e1 = fex2(sacc[nt][1] - mn0);
            float e2 = fex2(sacc[nt][2] - mn1);
            float e3 = fex2(sacc[nt][3] - mn1);
            ps0 += e0 + e1;
            ps1 += e2 + e3;
            const int cb = nt * 8;
            PWm [cb + cpa] = rnd(e0);
            PWm [cb + cpb] = rnd(e1);
            PWm8[cb + cpa] = rnd(e2);
            PWm8[cb + cpb] = rnd(e3);
        }
        ps0 += __shfl_xor_sync(0xffffffffu, ps0, 1);
        ps0 += __shfl_xor_sync(0xffffffffu, ps0, 2);
        ps1 += __shfl_xor_sync(0xffffffffu, ps1, 1);
        ps1 += __shfl_xor_sync(0xffffffffu, ps1, 2);
        l0 = l0 * a0 + ps0;
        l1 = l1 * a1 + ps1;
#pragma unroll
        for (int nt = 0; nt < 8; nt++) {
            oacc[nt][0] *= a0; oacc[nt][1] *= a0;
            oacc[nt][2] *= a1; oacc[nt][3] *= a1;
        }
        m0r = mn0; m1r = mn1;
        __syncwarp();

        // ---- O += P @ V  (32-key contraction = 4 k-steps) ----
        const float* PW = P + wid * 16 * SPP;
#pragma unroll
        for (int ks = 0; ks < 4; ks++) {
            const int ko = ks * 8 + 2 * tig;
            float2 plo = *(const float2*)(PW + g * SPP + ko);
            float2 phi = *(const float2*)(PW + (g + 8) * SPP + ko);
            uint32_t pa0 = __float_as_uint(plo.x);
            uint32_t pa1 = __float_as_uint(phi.x);
            uint32_t pa2 = __float_as_uint(plo.y);
            uint32_t pa3 = __float_as_uint(phi.y);
#pragma unroll
            for (int nt = 0; nt < 8; nt++) {
                float2 b = *(const float2*)(Vsh + (nt * 8 + g) * SPV + ko);
                mma_tf32(oacc[nt][0], oacc[nt][1], oacc[nt][2], oacc[nt][3],
                         pa0, pa1, pa2, pa3,
                         __float_as_uint(b.x), __float_as_uint(b.y));
            }
        }
    }

    // ---- normalize + store, K-permuted columns for the O-proj ----
    const float inv0 = 1.0f / l0;
    const float inv1 = 1.0f / l1;
    const int row0 = q0 + wid * 16 + g;
#pragma unroll
    for (int nt = 0; nt < 8; nt++) {
        const int base = h * HD + nt * 8;
        O[(size_t)row0 * EMB + base + cpa]       = rnd(oacc[nt][0] * inv0);
        O[(size_t)row0 * EMB + base + cpb]       = rnd(oacc[nt][1] * inv0);
        O[(size_t)(row0 + 8) * EMB + base + cpa] = rnd(oacc[nt][2] * inv1);
        O[(size_t)(row0 + 8) * EMB + base + cpb] = rnd(oacc[nt][3] * inv1);
    }
}

// ============================================================
// launch
// ============================================================
extern "C" void kernel_launch(void* const* d_in, const int* in_sizes, int n_in,
                              void* d_out, int out_size) {
    (void)in_sizes; (void)n_in; (void)out_size;
    const float* x  = (const float*)d_in[0];
    const float* Wq = (const float*)d_in[1];
    const float* Wk = (const float*)d_in[2];
    const float* Wv = (const float*)d_in[3];
    const float* Wo = (const float*)d_in[4];
    float* out = (float*)d_out;

    void *pQ, *pK, *pV, *pA, *px, *pwq, *pwo, *pwk, *pwv, *pkvp;
    cudaGetSymbolAddress(&pQ, g_Q);
    cudaGetSymbolAddress(&pK, g_K);
    cudaGetSymbolAddress(&pV, g_V);
    cudaGetSymbolAddress(&pA, g_A);
    cudaGetSymbolAddress(&px, g_x);
    cudaGetSymbolAddress(&pwq, g_wq);
    cudaGetSymbolAddress(&pwo, g_wo);
    cudaGetSymbolAddress(&pwk, g_wk);
    cudaGetSymbolAddress(&pwv, g_wv);
    cudaGetSymbolAddress(&pkvp, g_kvp);
    float* Qd = (float*)pQ;   float* Kd = (float*)pK;
    float* Vd = (float*)pV;   float* Ad = (float*)pA;
    float* xr = (float*)px;   float* wqr = (float*)pwq;
    float* wor = (float*)pwo; float* wkr = (float*)pwk;
    float* wvr = (float*)pwv; float* kvp = (float*)pkvp;

    cudaFuncSetAttribute(gemm_tf32mma, cudaFuncAttributeMaxDynamicSharedMemorySize, GEMM_SMEM);
    cudaFuncSetAttribute(attn_mma, cudaFuncAttributeMaxDynamicSharedMemorySize, ATT_SMEM);

    prep_pass<<<2048, 256>>>(x, Wq, Wo, Wk, Wv, xr, wqr, wor, wkr, wvr);

    gemm_tf32mma<<<384, 128, GEMM_SMEM>>>(
        xr, wqr, wkr, wvr, Qd, kvp, EMB, EMB, 3);
    kv_reduce<<<(T_SEQ * 128 / 4 + 255) / 256, 256>>>(kvp, Kd, Vd);
    attn_mma<<<dim3(T_SEQ / QROWS, NH), 128, ATT_SMEM>>>(Qd, Kd, Vd, Ad);
    gemm_tf32mma<<<dim3(EMB / 128, T_SEQ / 128), 128, GEMM_SMEM>>>(
        Ad, wor, nullptr, nullptr, out, nullptr, EMB, EMB, 0);
}

// round 13
// speedup vs baseline: 1.5907x; 1.0002x over previous
#include <cuda_runtime.h>
#include <cstdint>

#define T_SEQ 2048
#define EMB   2048
#define NH    32
#define HD    64
#define LOG2E 1.4426950408889634f

// -------- scratch (device globals) --------
__device__ float g_Q[T_SEQ * EMB];      // q proj (scaled, rounded, D-permuted)
__device__ float g_K[T_SEQ * HD];       // k proj (rounded, D-permuted)
__device__ float g_V[HD * T_SEQ];       // v proj TRANSPOSED Vt[d][t], key-permuted
__device__ float g_A[T_SEQ * EMB];      // attention out (rounded, K-permuted cols)
__device__ float g_x [T_SEQ * EMB];     // x  rounded+permuted
__device__ float g_wq[EMB * EMB];       // Wq rounded+permuted
__device__ float g_wo[EMB * EMB];       // Wo rounded+permuted
__device__ float g_wk[HD * EMB];        // Wk rounded+permuted
__device__ float g_wv[HD * EMB];        // Wv rounded+permuted
__device__ float g_kvp[8 * T_SEQ * 128];// KV split-K partials

// ============================================================
// helpers
// ============================================================
__device__ __forceinline__ uint32_t smem_u32(const void* p) {
    uint32_t a;
    asm("{ .reg .u64 t; cvta.to.shared.u64 t, %1; cvt.u32.u64 %0, t; }" : "=r"(a) : "l"(p));
    return a;
}
__device__ __forceinline__ uint32_t f2tf32(float x) {
    uint32_t r;
    asm("cvt.rna.tf32.f32 %0, %1;" : "=r"(r) : "f"(x));
    return r;
}
__device__ __forceinline__ float rnd(float x) { return __uint_as_float(f2tf32(x)); }
__device__ __forceinline__ float fex2(float x) {
    float r;
    asm("ex2.approx.f32 %0, %1;" : "=f"(r) : "f"(x));
    return r;
}
__device__ __forceinline__ void cp16(uint32_t dst, const void* src) {
    asm volatile("cp.async.cg.shared.global [%0], [%1], 16;" :: "r"(dst), "l"(src) : "memory");
}
__device__ __forceinline__ void mma_tf32(float& d0, float& d1, float& d2, float& d3,
                                         uint32_t a0, uint32_t a1, uint32_t a2, uint32_t a3,
                                         uint32_t b0, uint32_t b1) {
    asm volatile("mma.sync.aligned.m16n8k8.row.col.f32.tf32.tf32.f32 "
                 "{%0,%1,%2,%3}, {%4,%5,%6,%7}, {%8,%9}, {%0,%1,%2,%3};"
                 : "+f"(d0), "+f"(d1), "+f"(d2), "+f"(d3)
                 : "r"(a0), "r"(a1), "r"(a2), "r"(a3), "r"(b0), "r"(b1));
}

// ============================================================
// fused round+permute prep: per 8-group out[2j]=in[j], out[2j+1]=in[j+4]
// ============================================================
#define NG_BIG (T_SEQ * EMB / 8)
#define NG_W   (HD * EMB / 8)

__global__ void prep_pass(const float* __restrict__ x,  const float* __restrict__ wq,
                          const float* __restrict__ wo, const float* __restrict__ wk,
                          const float* __restrict__ wv,
                          float* __restrict__ xr,  float* __restrict__ wqr,
                          float* __restrict__ wor, float* __restrict__ wkr,
                          float* __restrict__ wvr) {
    const int total = 3 * NG_BIG + 2 * NG_W;
    for (int gi = blockIdx.x * blockDim.x + threadIdx.x; gi < total;
         gi += gridDim.x * blockDim.x) {
        const float* src; float* dst; int off;
        if (gi < NG_BIG)                { src = x;  dst = xr;  off = gi; }
        else if (gi < 2 * NG_BIG)       { src = wq; dst = wqr; off = gi - NG_BIG; }
        else if (gi < 3 * NG_BIG)       { src = wo; dst = wor; off = gi - 2 * NG_BIG; }
        else if (gi < 3 * NG_BIG + NG_W){ src = wk; dst = wkr; off = gi - 3 * NG_BIG; }
        else                            { src = wv; dst = wvr; off = gi - 3 * NG_BIG - NG_W; }
        float4 a = *(const float4*)(src + (size_t)off * 8);
        float4 b = *(const float4*)(src + (size_t)off * 8 + 4);
        float4 o0 = make_float4(rnd(a.x), rnd(b.x), rnd(a.y), rnd(b.y));
        float4 o1 = make_float4(rnd(a.z), rnd(b.z), rnd(a.w), rnd(b.w));
        *(float4*)(dst + (size_t)off * 8)     = o0;
        *(float4*)(dst + (size_t)off * 8 + 4) = o1;
    }
}

// ============================================================
// tf32 mma.sync GEMM, K-permuted operands, 64x64 warp tiles.
// (unchanged from R11/R12)
// ============================================================
#define BKF 32
#define LDA 40
#define OPER_F (128 * LDA)
#define GEMM_SMEM (2 * 2 * OPER_F * 4)        // 81920 bytes

__global__ __launch_bounds__(128, 2) void gemm_tf32mma(
    const float* __restrict__ A, const float* __restrict__ B0,
    const float* __restrict__ B1, const float* __restrict__ B2,
    float* __restrict__ C, float* __restrict__ C2,
    int K, int N, int mode) {
    extern __shared__ float sm[];
    const int tid  = threadIdx.x;
    const int wid  = tid >> 5;
    const int lane = tid & 31;
    const int wm   = wid & 1;
    const int wn   = wid >> 1;
    const int g    = lane >> 2;
    const int tig  = lane & 3;

    int role, m0, n0, kbeg, NT, do_round, do_perm;
    float oscale;
    float* Cout;
    if (mode == 3) {
        if (blockIdx.x < 256) {
            role = 0; do_perm = 1; do_round = 1; oscale = 0.125f * LOG2E;
            n0 = (blockIdx.x & 15) * 128; m0 = (blockIdx.x >> 4) * 128;
            kbeg = 0; NT = K / BKF; Cout = C;
        } else {
            role = 2; do_perm = 0; do_round = 0; oscale = 1.0f;
            const int b = blockIdx.x - 256;
            kbeg = (b & 7) * 256; m0 = (b >> 3) * 128; n0 = 0; NT = 256 / BKF;
            Cout = C2 + (size_t)(b & 7) * T_SEQ * 128;
        }
    } else {
        role = 0; do_perm = 0; do_round = 0; oscale = 1.0f;
        n0 = blockIdx.x * 128; m0 = blockIdx.y * 128;
        kbeg = 0; NT = K / BKF; Cout = C;
    }

    float acc[4][8][4];
#pragma unroll
    for (int i = 0; i < 4; i++)
#pragma unroll
        for (int j = 0; j < 8; j++)
#pragma unroll
            for (int r = 0; r < 4; r++) acc[i][j][r] = 0.f;

    auto stage = [&](int t, int b) {
        float* dstA = sm + b * 2 * OPER_F;
        float* dstB = dstA + OPER_F;
        const int kof = kbeg + t * BKF;
#pragma unroll
        for (int u = 0; u < 8; u++) {
            int idx = u * 128 + tid;
            int r = idx >> 3, c4 = idx & 7;
            cp16(smem_u32(dstA + r * LDA + c4 * 4),
                 A + (size_t)(m0 + r) * K + kof + c4 * 4);
            const float* gb;
            if (role == 2) gb = (r < 64 ? B1 + (size_t)r * K : B2 + (size_t)(r - 64) * K)
                                + kof + c4 * 4;
            else           gb = B0 + (size_t)(n0 + r) * K + kof + c4 * 4;
            cp16(smem_u32(dstB + r * LDA + c4 * 4), gb);
        }
        asm volatile("cp.async.commit_group;" ::: "memory");
    };

    stage(0, 0);

    for (int t = 0; t < NT; t++) {
        if (t + 1 < NT) {
            stage(t + 1, (t + 1) & 1);
            asm volatile("cp.async.wait_group 1;" ::: "memory");
        } else {
            asm volatile("cp.async.wait_group 0;" ::: "memory");
        }
        __syncthreads();

        const float* sA = sm + (t & 1) * 2 * OPER_F + (wm * 64) * LDA;
        const float* sB = sm + (t & 1) * 2 * OPER_F + OPER_F + (wn * 64) * LDA;

#pragma unroll
        for (int ks = 0; ks < 4; ks++) {
            const int ko = ks * 8 + 2 * tig;
            uint32_t bf[8][2];
#pragma unroll
            for (int nt = 0; nt < 8; nt++) {
                float2 b = *(const float2*)(sB + (nt * 8 + g) * LDA + ko);
                bf[nt][0] = __float_as_uint(b.x);
                bf[nt][1] = __float_as_uint(b.y);
            }
            uint32_t af[4][4];
#pragma unroll
            for (int mt = 0; mt < 4; mt++) {
                float2 alo = *(const float2*)(sA + (mt * 16 + g) * LDA + ko);
                float2 ahi = *(const float2*)(sA + (mt * 16 + 8 + g) * LDA + ko);
                af[mt][0] = __float_as_uint(alo.x);
                af[mt][1] = __float_as_uint(ahi.x);
                af[mt][2] = __float_as_uint(alo.y);
                af[mt][3] = __float_as_uint(ahi.y);
            }
#pragma unroll
            for (int mt = 0; mt < 4; mt++)
#pragma unroll
                for (int nt = 0; nt < 8; nt++)
                    mma_tf32(acc[mt][nt][0], acc[mt][nt][1], acc[mt][nt][2], acc[mt][nt][3],
                             af[mt][0], af[mt][1], af[mt][2], af[mt][3],
                             bf[nt][0], bf[nt][1]);
        }
        __syncthreads();
    }

    const int cpa = 2 * ((2 * tig) & 3) + ((2 * tig) >> 2);
    const int cpb = 2 * ((2 * tig + 1) & 3) + ((2 * tig + 1) >> 2);
#pragma unroll
    for (int mt = 0; mt < 4; mt++) {
        const int row0 = m0 + wm * 64 + mt * 16 + g;
#pragma unroll
        for (int nt = 0; nt < 8; nt++) {
            float v0 = acc[mt][nt][0] * oscale, v1 = acc[mt][nt][1] * oscale;
            float v2 = acc[mt][nt][2] * oscale, v3 = acc[mt][nt][3] * oscale;
            if (do_round) { v0 = rnd(v0); v1 = rnd(v1); v2 = rnd(v2); v3 = rnd(v3); }
            const int colL = wn * 64 + nt * 8;
            if (role == 2) {
                const int c = colL + 2 * tig;
                *(float2*)(Cout + (size_t)row0 * 128 + c)       = make_float2(v0, v1);
                *(float2*)(Cout + (size_t)(row0 + 8) * 128 + c) = make_float2(v2, v3);
            } else if (do_perm) {
                const int cb = n0 + colL;
                Cout[(size_t)row0 * N + cb + cpa]       = v0;
                Cout[(size_t)row0 * N + cb + cpb]       = v1;
                Cout[(size_t)(row0 + 8) * N + cb + cpa] = v2;
                Cout[(size_t)(row0 + 8) * N + cb + cpb] = v3;
            } else {
                const int col = n0 + colL + 2 * tig;
                *(float2*)(Cout + (size_t)row0 * N + col)       = make_float2(v0, v1);
                *(float2*)(Cout + (size_t)(row0 + 8) * N + col) = make_float2(v2, v3);
            }
        }
    }
}

// ============================================================
// KV reduce (unchanged)
// ============================================================
__global__ void kv_reduce(const float* __restrict__ part,
                          float* __restrict__ Kd, float* __restrict__ Vt) {
    const int n4 = T_SEQ * 128 / 4;
    int idx = blockIdx.x * blockDim.x + threadIdx.x;
    if (idx >= n4) return;
    float4 s = *(const float4*)(part + (size_t)idx * 4);
#pragma unroll
    for (int p = 1; p < 8; p++) {
        float4 v = *(const float4*)(part + (size_t)p * T_SEQ * 128 + (size_t)idx * 4);
        s.x += v.x; s.y += v.y; s.z += v.z; s.w += v.w;
    }
    s.x = rnd(s.x); s.y = rnd(s.y); s.z = rnd(s.z); s.w = rnd(s.w);
    const int t = (idx * 4) >> 7;
    const int c = (idx * 4) & 127;
    if (c < 64) {
        const int base = t * 64 + (c & ~7);
        const int o = (c & 4) ? 1 : 0;
        Kd[base + o + 0] = s.x;
        Kd[base + o + 2] = s.y;
        Kd[base + o + 4] = s.z;
        Kd[base + o + 6] = s.w;
    } else {
        const int d = c - 64;
        const int permt = (t & ~7) + 2 * (t & 3) + ((t >> 2) & 1);
        Vt[(size_t)(d + 0) * T_SEQ + permt] = s.x;
        Vt[(size_t)(d + 1) * T_SEQ + permt] = s.y;
        Vt[(size_t)(d + 2) * T_SEQ + permt] = s.z;
        Vt[(size_t)(d + 3) * T_SEQ + permt] = s.w;
    }
}

// ============================================================
// Flash attention — 32-key tiles, 2 smem buffers, one barrier
// per tile: wait 0 -> sync -> prefetch(t+1) -> compute(t).
// __launch_bounds__(128, 4): 4 CTAs/SM (smem 48 KB/CTA).
// ============================================================
#define SPK 72
#define SPV 40
#define SPP 40
#define TKEY 32
#define KBUF (TKEY * SPK)          // 2304 floats
#define VBUF (64 * SPV)            // 2560 floats
#define QROWS 64
#define ATT_SMEM ((2 * KBUF + 2 * VBUF + QROWS * SPP) * 4)   // 49152 B

__global__ __launch_bounds__(128, 4) void attn_mma(const float* __restrict__ Q,
                                                   const float* __restrict__ Kg,
                                                   const float* __restrict__ Vt,
                                                   float* __restrict__ O) {
    extern __shared__ float sm[];
    float* Kbase = sm;                       // 2 x [32][SPK]
    float* Vbase = sm + 2 * KBUF;            // 2 x [64][SPV]
    float* P     = sm + 2 * KBUF + 2 * VBUF; // [64][SPP]

    const int h   = blockIdx.y;
    const int q0  = (gridDim.x - 1 - blockIdx.x) * QROWS;   // largest-first
    const int tid = threadIdx.x;
    const int wid = tid >> 5;
    const int lane = tid & 31;
    const int g   = lane >> 2;
    const int tig = lane & 3;
    const float slope2 = exp2f(-0.25f * (float)(h + 1)) * LOG2E;

    // ---- stage Q (scaled/rounded/D-permuted) into K-buffer region ----
    // 64 rows x 64 floats, stride SPK (region holds 2*2304 = 4608 >= 63*72+64)
#pragma unroll
    for (int u = 0; u < 8; u++) {
        int idx = u * 128 + tid;
        int r = idx >> 4, c4 = idx & 15;
        *(float4*)(Kbase + r * SPK + c4 * 4) =
            *(const float4*)(Q + (size_t)(q0 + r) * EMB + h * HD + c4 * 4);
    }
    __syncthreads();

    uint32_t qf[8][4];
    {
        const float* QW = Kbase + wid * 16 * SPK;
#pragma unroll
        for (int ks = 0; ks < 8; ks++) {
            const int ko = ks * 8 + 2 * tig;
            float2 lo = *(const float2*)(QW + g * SPK + ko);
            float2 hi = *(const float2*)(QW + (g + 8) * SPK + ko);
            qf[ks][0] = __float_as_uint(lo.x);
            qf[ks][1] = __float_as_uint(hi.x);
            qf[ks][2] = __float_as_uint(lo.y);
            qf[ks][3] = __float_as_uint(hi.y);
        }
    }
    __syncthreads();   // all warps read Q before prefetch overwrites

    // ---- prefetch helper: tile t -> buffer t&1 ----
    auto prefetch = [&](int t) {
        const int b = t & 1;
        const int j0 = t * TKEY;
        float* Kb = Kbase + b * KBUF;
        float* Vb = Vbase + b * VBUF;
#pragma unroll
        for (int u = 0; u < 4; u++) {
            int idx = u * 128 + tid;
            int kr = idx >> 4, kc = idx & 15;
            cp16(smem_u32(Kb + kr * SPK + kc * 4), Kg + (size_t)(j0 + kr) * HD + kc * 4);
            int vr = idx >> 3, vc = idx & 7;
            cp16(smem_u32(Vb + vr * SPV + vc * 4), Vt + (size_t)vr * T_SEQ + j0 + vc * 4);
        }
        asm volatile("cp.async.commit_group;" ::: "memory");
    };

    float oacc[8][4];
#pragma unroll
    for (int nt = 0; nt < 8; nt++)
#pragma unroll
        for (int r = 0; r < 4; r++) oacc[nt][r] = 0.f;

    float m0r = -1e30f, m1r = -1e30f;
    float l0 = 0.f, l1 = 0.f;
    const int i0 = q0 + wid * 16 + g;
    const int i1 = i0 + 8;
    float* PWm  = P + (wid * 16 + g) * SPP;
    float* PWm8 = PWm + 8 * SPP;
    const int cpa = 2 * ((2 * tig) & 3) + ((2 * tig) >> 2);
    const int cpb = 2 * ((2 * tig + 1) & 3) + ((2 * tig + 1) >> 2);

    const int NTILE = (q0 + QROWS) / TKEY;
    prefetch(0);

    for (int t = 0; t < NTILE; t++) {
        const int j0 = t * TKEY;
        asm volatile("cp.async.wait_group 0;" ::: "memory");
        __syncthreads();        // tile t visible; compute(t-1) closed
        if (t + 1 < NTILE) prefetch(t + 1);   // buffer (t-1)&1 — safe post-barrier

        const float* Ksh = Kbase + (t & 1) * KBUF;
        const float* Vsh = Vbase + (t & 1) * VBUF;

        // ---- S = Q @ K^T (32 keys) ----
        float sacc[4][4];
#pragma unroll
        for (int nt = 0; nt < 4; nt++)
#pragma unroll
            for (int r = 0; r < 4; r++) sacc[nt][r] = 0.f;

#pragma unroll
        for (int ks = 0; ks < 8; ks++) {
            const int ko = ks * 8 + 2 * tig;
#pragma unroll
            for (int nt = 0; nt < 4; nt++) {
                float2 b = *(const float2*)(Ksh + (nt * 8 + g) * SPK + ko);
                mma_tf32(sacc[nt][0], sacc[nt][1], sacc[nt][2], sacc[nt][3],
                         qf[ks][0], qf[ks][1], qf[ks][2], qf[ks][3],
                         __float_as_uint(b.x), __float_as_uint(b.y));
            }
        }

        // ---- ALiBi + causal mask, tile max ----
        float mx0 = -1e30f, mx1 = -1e30f;
#pragma unroll
        for (int nt = 0; nt < 4; nt++) {
            const int jb = j0 + nt * 8 + 2 * tig;
            float v0 = (jb     <= i0) ? fmaf(slope2, (float)(jb     - i0), sacc[nt][0]) : -1e30f;
            float v1 = (jb + 1 <= i0) ? fmaf(slope2, (float)(jb + 1 - i0), sacc[nt][1]) : -1e30f;
            float v2 = (jb     <= i1) ? fmaf(slope2, (float)(jb     - i1), sacc[nt][2]) : -1e30f;
            float v3 = (jb + 1 <= i1) ? fmaf(slope2, (float)(jb + 1 - i1), sacc[nt][3]) : -1e30f;
            sacc[nt][0] = v0; sacc[nt][1] = v1; sacc[nt][2] = v2; sacc[nt][3] = v3;
            mx0 = fmaxf(mx0, fmaxf(v0, v1));
            mx1 = fmaxf(mx1, fmaxf(v2, v3));
        }
        mx0 = fmaxf(mx0, __shfl_xor_sync(0xffffffffu, mx0, 1));
        mx0 = fmaxf(mx0, __shfl_xor_sync(0xffffffffu, mx0, 2));
        mx1 = fmaxf(mx1, __shfl_xor_sync(0xffffffffu, mx1, 1));
        mx1 = fmaxf(mx1, __shfl_xor_sync(0xffffffffu, mx1, 2));

        const float mn0 = fmaxf(m0r, mx0);
        const float mn1 = fmaxf(m1r, mx1);
        const float a0 = fex2(m0r - mn0);
        const float a1 = fex2(m1r - mn1);

        float ps0 = 0.f, ps1 = 0.f;
#pragma unroll
        for (int nt = 0; nt < 4; nt++) {
            float e0 = fex2(sacc[nt][0] - mn0);
            float e1 = fex2(sacc[nt][1] - mn0);
            float e2 = fex2(sacc[nt][2] - mn1);
            float e3 = fex2(sacc[nt][3] - mn1);
            ps0 += e0 + e1;
            ps1 += e2 + e3;
            const int cb = nt * 8;
            PWm [cb + cpa] = rnd(e0);
            PWm [cb + cpb] = rnd(e1);
            PWm8[cb + cpa] = rnd(e2);
            PWm8[cb + cpb] = rnd(e3);
        }
        ps0 += __shfl_xor_sync(0xffffffffu, ps0, 1);
        ps0 += __shfl_xor_sync(0xffffffffu, ps0, 2);
        ps1 += __shfl_xor_sync(0xffffffffu, ps1, 1);
        ps1 += __shfl_xor_sync(0xffffffffu, ps1, 2);
        l0 = l0 * a0 + ps0;
        l1 = l1 * a1 + ps1;
#pragma unroll
        for (int nt = 0; nt < 8; nt++) {
            oacc[nt][0] *= a0; oacc[nt][1] *= a0;
            oacc[nt][2] *= a1; oacc[nt][3] *= a1;
        }
        m0r = mn0; m1r = mn1;
        __syncwarp();

        // ---- O += P @ V  (32-key contraction = 4 k-steps) ----
        const float* PW = P + wid * 16 * SPP;
#pragma unroll
        for (int ks = 0; ks < 4; ks++) {
            const int ko = ks * 8 + 2 * tig;
            float2 plo = *(const float2*)(PW + g * SPP + ko);
            float2 phi = *(const float2*)(PW + (g + 8) * SPP + ko);
            uint32_t pa0 = __float_as_uint(plo.x);
            uint32_t pa1 = __float_as_uint(phi.x);
            uint32_t pa2 = __float_as_uint(plo.y);
            uint32_t pa3 = __float_as_uint(phi.y);
#pragma unroll
            for (int nt = 0; nt < 8; nt++) {
                float2 b = *(const float2*)(Vsh + (nt * 8 + g) * SPV + ko);
                mma_tf32(oacc[nt][0], oacc[nt][1], oacc[nt][2], oacc[nt][3],
                         pa0, pa1, pa2, pa3,
                         __float_as_uint(b.x), __float_as_uint(b.y));
            }
        }
    }

    // ---- normalize + store, K-permuted columns for the O-proj ----
    const float inv0 = 1.0f / l0;
    const float inv1 = 1.0f / l1;
    const int row0 = q0 + wid * 16 + g;
#pragma unroll
    for (int nt = 0; nt < 8; nt++) {
        const int base = h * HD + nt * 8;
        O[(size_t)row0 * EMB + base + cpa]       = rnd(oacc[nt][0] * inv0);
        O[(size_t)row0 * EMB + base + cpb]       = rnd(oacc[nt][1] * inv0);
        O[(size_t)(row0 + 8) * EMB + base + cpa] = rnd(oacc[nt][2] * inv1);
        O[(size_t)(row0 + 8) * EMB + base + cpb] = rnd(oacc[nt][3] * inv1);
    }
}

// ============================================================
// launch
// ============================================================
extern "C" void kernel_launch(void* const* d_in, const int* in_sizes, int n_in,
                              void* d_out, int out_size) {
    (void)in_sizes; (void)n_in; (void)out_size;
    const float* x  = (const float*)d_in[0];
    const float* Wq = (const float*)d_in[1];
    const float* Wk = (const float*)d_in[2];
    const float* Wv = (const float*)d_in[3];
    const float* Wo = (const float*)d_in[4];
    float* out = (float*)d_out;

    void *pQ, *pK, *pV, *pA, *px, *pwq, *pwo, *pwk, *pwv, *pkvp;
    cudaGetSymbolAddress(&pQ, g_Q);
    cudaGetSymbolAddress(&pK, g_K);
    cudaGetSymbolAddress(&pV, g_V);
    cudaGetSymbolAddress(&pA, g_A);
    cudaGetSymbolAddress(&px, g_x);
    cudaGetSymbolAddress(&pwq, g_wq);
    cudaGetSymbolAddress(&pwo, g_wo);
    cudaGetSymbolAddress(&pwk, g_wk);
    cudaGetSymbolAddress(&pwv, g_wv);
    cudaGetSymbolAddress(&pkvp, g_kvp);
    float* Qd = (float*)pQ;   float* Kd = (float*)pK;
    float* Vd = (float*)pV;   float* Ad = (float*)pA;
    float* xr = (float*)px;   float* wqr = (float*)pwq;
    float* wor = (float*)pwo; float* wkr = (float*)pwk;
    float* wvr = (float*)pwv; float* kvp = (float*)pkvp;

    cudaFuncSetAttribute(gemm_tf32mma, cudaFuncAttributeMaxDynamicSharedMemorySize, GEMM_SMEM);
    cudaFuncSetAttribute(attn_mma, cudaFuncAttributeMaxDynamicSharedMemorySize, ATT_SMEM);

    prep_pass<<<2048, 256>>>(x, Wq, Wo, Wk, Wv, xr, wqr, wor, wkr, wvr);

    gemm_tf32mma<<<384, 128, GEMM_SMEM>>>(
        xr, wqr, wkr, wvr, Qd, kvp, EMB, EMB, 3);
    kv_reduce<<<(T_SEQ * 128 / 4 + 255) / 256, 256>>>(kvp, Kd, Vd);
    attn_mma<<<dim3(T_SEQ / QROWS, NH), 128, ATT_SMEM>>>(Qd, Kd, Vd, Ad);
    gemm_tf32mma<<<dim3(EMB / 128, T_SEQ / 128), 128, GEMM_SMEM>>>(
        Ad, wor, nullptr, nullptr, out, nullptr, EMB, EMB, 0);
}